// round 13
// baseline (speedup 1.0000x reference)
#include <cuda_runtime.h>
#include <cuda_bf16.h>
#include <math.h>
#include <stdint.h>

// ---------------- problem constants ----------------
#define SEQ   512
#define DIM   1024
#define NHEAD 16
#define DHEAD 64
#define BATCH 4
#define VOCAB 16386
#define VPAD  16512        // 129 * 128
#define NLAYER 12
#define MTOK  (BATCH*SEQ)   // 2048
#define NQT   (SEQ/128)     // 4 q-tiles

// ---------------- scratch (device globals; no allocation) ----------------
__device__ float g_h[MTOK*DIM];                                  // residual (fp32)
__device__ float g_qkv[MTOK*3*DIM];                              // qkv (fp32, attn input)
__device__ __nv_bfloat16 g_xh[MTOK*DIM],   g_xl[MTOK*DIM];       // activation hi/lo
__device__ __nv_bfloat16 g_mh[MTOK*4*DIM], g_ml[MTOK*4*DIM];     // mlp mid hi/lo

// pre-split bf16 hi/lo weights (written every launch)
__device__ __nv_bfloat16 g_wqkv_h[NLAYER*DIM*3*DIM], g_wqkv_l[NLAYER*DIM*3*DIM];
__device__ __nv_bfloat16 g_watp_h[NLAYER*DIM*DIM],   g_watp_l[NLAYER*DIM*DIM];
__device__ __nv_bfloat16 g_wfc_h [NLAYER*DIM*4*DIM], g_wfc_l [NLAYER*DIM*4*DIM];
__device__ __nv_bfloat16 g_wmlp_h[NLAYER*4*DIM*DIM], g_wmlp_l[NLAYER*4*DIM*DIM];
__device__ __nv_bfloat16 g_whead_h[DIM*VPAD],        g_whead_l[DIM*VPAD];

// ---------------- split helpers ----------------
__device__ __forceinline__ void split2(float a, __nv_bfloat16& hi, __nv_bfloat16& lo) {
    hi = __float2bfloat16(a);
    lo = __float2bfloat16(a - __bfloat162float(hi));
}
__device__ __forceinline__ void split_pack(float a, float b, uint32_t& hi, uint32_t& lo) {
    __nv_bfloat16 ah, al, bh, bl;
    split2(a, ah, al); split2(b, bh, bl);
    __nv_bfloat162 H(ah, bh), L(al, bl);
    hi = *(uint32_t*)&H; lo = *(uint32_t*)&L;
}

// ---------------- weight pre-split kernels ----------------
__global__ void wsplit_kernel(const float* __restrict__ w,
                              __nv_bfloat16* __restrict__ hi,
                              __nv_bfloat16* __restrict__ lo, int n4) {
    int i = blockIdx.x * blockDim.x + threadIdx.x;
    if (i >= n4) return;
    float4 v = ((const float4*)w)[i];
    __nv_bfloat16 h0,h1,h2,h3,l0,l1,l2,l3;
    split2(v.x,h0,l0); split2(v.y,h1,l1); split2(v.z,h2,l2); split2(v.w,h3,l3);
    __nv_bfloat162* ph = (__nv_bfloat162*)hi + 2*i;
    __nv_bfloat162* pl = (__nv_bfloat162*)lo + 2*i;
    ph[0] = __nv_bfloat162(h0,h1); ph[1] = __nv_bfloat162(h2,h3);
    pl[0] = __nv_bfloat162(l0,l1); pl[1] = __nv_bfloat162(l2,l3);
}
__global__ void wsplit_head_kernel(const float* __restrict__ w,
                                   __nv_bfloat16* __restrict__ hi,
                                   __nv_bfloat16* __restrict__ lo) {
    int col = blockIdx.x * blockDim.x + threadIdx.x;
    int row = blockIdx.y;
    if (col >= VPAD) return;
    float v = (col < VOCAB) ? w[(size_t)row * VOCAB + col] : 0.f;
    __nv_bfloat16 h, l; split2(v, h, l);
    hi[(size_t)row * VPAD + col] = h;
    lo[(size_t)row * VPAD + col] = l;
}

// ---------------- embedding ----------------
__global__ void embed_kernel(const int* __restrict__ ids, const int* __restrict__ tts,
                             const float* __restrict__ wte, const float* __restrict__ wtte,
                             const float* __restrict__ wpe, float* __restrict__ out) {
    int row = blockIdx.x;
    int s   = row & (SEQ - 1);
    int id  = ids[row];
    int tt  = tts[row];
    const float4* te = (const float4*)(wte  + (size_t)id * DIM);
    const float4* ty = (const float4*)(wtte + (size_t)tt * DIM);
    const float4* pe = (const float4*)(wpe  + (size_t)s  * DIM);
    float4* o = (float4*)(out + (size_t)row * DIM);
    int i = threadIdx.x;
    float4 a = te[i], b = ty[i], c = pe[i];
    o[i] = make_float4(a.x + b.x + c.x, a.y + b.y + c.y,
                       a.z + b.z + c.z, a.w + b.w + c.w);
}

// ---------------- block reduction helper (256 threads) ----------------
__device__ __forceinline__ float blockSum256(float v, float* red) {
    #pragma unroll
    for (int o = 16; o > 0; o >>= 1) v += __shfl_xor_sync(0xffffffffu, v, o);
    if ((threadIdx.x & 31) == 0) red[threadIdx.x >> 5] = v;
    __syncthreads();
    if (threadIdx.x == 0) {
        float t = 0.f;
        #pragma unroll
        for (int i = 0; i < 8; i++) t += red[i];
        red[0] = t;
    }
    __syncthreads();
    float r = red[0];
    __syncthreads();
    return r;
}

// ---------------- layernorm -> bf16 hi/lo ----------------
__global__ void ln_bf_kernel(const float* __restrict__ in,
                             __nv_bfloat16* __restrict__ oh, __nv_bfloat16* __restrict__ ol,
                             const float* __restrict__ w, const float* __restrict__ b) {
    __shared__ float red[8];
    int row = blockIdx.x;
    int t = threadIdx.x;
    const float4* ip = (const float4*)(in + (size_t)row * DIM);
    float4 v = ip[t];
    float s  = v.x + v.y + v.z + v.w;
    float sq = v.x*v.x + v.y*v.y + v.z*v.z + v.w*v.w;
    float tot  = blockSum256(s,  red);
    float tot2 = blockSum256(sq, red);
    float mean = tot * (1.0f / DIM);
    float var  = tot2 * (1.0f / DIM) - mean * mean;
    float rstd = rsqrtf(var + 1e-5f);
    const float4 w4 = ((const float4*)w)[t];
    const float4 b4 = ((const float4*)b)[t];
    float o0 = (v.x - mean) * rstd * w4.x + b4.x;
    float o1 = (v.y - mean) * rstd * w4.y + b4.y;
    float o2 = (v.z - mean) * rstd * w4.z + b4.z;
    float o3 = (v.w - mean) * rstd * w4.w + b4.w;
    __nv_bfloat16 h0,h1,h2,h3,l0,l1,l2,l3;
    split2(o0,h0,l0); split2(o1,h1,l1); split2(o2,h2,l2); split2(o3,h3,l3);
    size_t off = (size_t)row * DIM + t * 4;
    *(__nv_bfloat162*)(oh + off)     = __nv_bfloat162(h0, h1);
    *(__nv_bfloat162*)(oh + off + 2) = __nv_bfloat162(h2, h3);
    *(__nv_bfloat162*)(ol + off)     = __nv_bfloat162(l0, l1);
    *(__nv_bfloat162*)(ol + off + 2) = __nv_bfloat162(l2, l3);
}

// ---------------- GELU ----------------
__device__ __forceinline__ float gelu_f(float x) {
    const float c0 = 0.7978845608028654f;
    const float c1 = 0.044715f;
    float x3 = x * x * x;
    return 0.5f * x * (1.0f + tanhf(c0 * (x + c1 * x3)));
}

// ---------------- tensor-core primitives ----------------
__device__ __forceinline__ uint32_t smem_u32(const void* p) {
    return (uint32_t)__cvta_generic_to_shared(p);
}
__device__ __forceinline__ void ldsm4(uint32_t addr, uint32_t* r) {
    asm volatile("ldmatrix.sync.aligned.m8n8.x4.shared.b16 {%0,%1,%2,%3},[%4];\n"
                 : "=r"(r[0]), "=r"(r[1]), "=r"(r[2]), "=r"(r[3]) : "r"(addr));
}
__device__ __forceinline__ void ldsm2t(uint32_t addr, uint32_t* r) {
    asm volatile("ldmatrix.sync.aligned.m8n8.x2.trans.shared.b16 {%0,%1},[%2];\n"
                 : "=r"(r[0]), "=r"(r[1]) : "r"(addr));
}
__device__ __forceinline__ void mma16816(float* c, const uint32_t* a, const uint32_t* b) {
    asm volatile("mma.sync.aligned.m16n8k16.row.col.f32.bf16.bf16.f32 "
                 "{%0,%1,%2,%3},{%4,%5,%6,%7},{%8,%9},{%0,%1,%2,%3};\n"
                 : "+f"(c[0]), "+f"(c[1]), "+f"(c[2]), "+f"(c[3])
                 : "r"(a[0]), "r"(a[1]), "r"(a[2]), "r"(a[3]), "r"(b[0]), "r"(b[1]));
}
__device__ __forceinline__ void cpasync16(uint32_t dst, const void* src) {
    asm volatile("cp.async.cg.shared.global [%0], [%1], 16;\n" :: "r"(dst), "l"(src));
}
__device__ __forceinline__ void cpasync_commit() {
    asm volatile("cp.async.commit_group;\n");
}
__device__ __forceinline__ void cpasync_wait1() {
    asm volatile("cp.async.wait_group 1;\n");
}

// ---------------- flash attention (bf16 hi/lo output) ----------------
#define FA_ST 72
#define FA_TILE (128*FA_ST)

__device__ __forceinline__ void stage128x64(const float* __restrict__ src,
                                            __nv_bfloat16* sh, __nv_bfloat16* sl,
                                            int tid, float scale) {
    #pragma unroll
    for (int i = 0; i < 8; i++) {
        int idx = i * 256 + tid;
        int row = idx >> 4, c = (idx & 15) * 4;
        float4 v = *(const float4*)(src + (size_t)row * (3 * DIM) + c);
        v.x *= scale; v.y *= scale; v.z *= scale; v.w *= scale;
        __nv_bfloat16 h0, h1, h2, h3, l0, l1, l2, l3;
        split2(v.x, h0, l0); split2(v.y, h1, l1);
        split2(v.z, h2, l2); split2(v.w, h3, l3);
        __nv_bfloat162* ph = (__nv_bfloat162*)&sh[row * FA_ST + c];
        __nv_bfloat162* pl = (__nv_bfloat162*)&sl[row * FA_ST + c];
        ph[0] = __nv_bfloat162(h0, h1); ph[1] = __nv_bfloat162(h2, h3);
        pl[0] = __nv_bfloat162(l0, l1); pl[1] = __nv_bfloat162(l2, l3);
    }
}

__global__ __launch_bounds__(256, 1)
void flash_attn_kernel(const float* __restrict__ qkv,
                       __nv_bfloat16* __restrict__ xh, __nv_bfloat16* __restrict__ xl) {
    extern __shared__ __nv_bfloat16 fasmem[];
    __nv_bfloat16* QKh = fasmem;
    __nv_bfloat16* QKl = fasmem + FA_TILE;
    __nv_bfloat16* Vh  = fasmem + 2 * FA_TILE;
    __nv_bfloat16* Vl  = fasmem + 3 * FA_TILE;

    const int qt = (NQT - 1) - blockIdx.x;
    const int h  = blockIdx.y, b = blockIdx.z;
    const int tid = threadIdx.x, lane = tid & 31, w = tid >> 5;

    const float* qbase = qkv + ((size_t)(b * SEQ + qt * 128)) * (3 * DIM) + h * DHEAD;
    stage128x64(qbase, QKh, QKl, tid, 0.125f);
    __syncthreads();

    uint32_t qfh[4][4], qfl[4][4];
    {
        uint32_t qaH = smem_u32(&QKh[(w * 16 + (lane & 15)) * FA_ST + (lane >> 4) * 8]);
        uint32_t qaL = smem_u32(&QKl[(w * 16 + (lane & 15)) * FA_ST + (lane >> 4) * 8]);
        #pragma unroll
        for (int d = 0; d < 4; d++) { ldsm4(qaH + d * 32, qfh[d]); ldsm4(qaL + d * 32, qfl[d]); }
    }

    float m0 = -1e30f, m1 = -1e30f, l0 = 0.f, l1 = 0.f;
    float oacc[8][4];
    #pragma unroll
    for (int j = 0; j < 8; j++)
        #pragma unroll
        for (int t = 0; t < 4; t++) oacc[j][t] = 0.f;

    const int nkt = qt + 1;
    for (int kt = 0; kt < nkt; kt++) {
        __syncthreads();
        const float* kb = qkv + ((size_t)(b * SEQ + kt * 128)) * (3 * DIM) + DIM + h * DHEAD;
        stage128x64(kb,       QKh, QKl, tid, 1.f);
        stage128x64(kb + DIM, Vh,  Vl,  tid, 1.f);
        __syncthreads();

        float sacc[8][2][4];
        #pragma unroll
        for (int ng = 0; ng < 8; ng++)
            #pragma unroll
            for (int nt = 0; nt < 2; nt++)
                #pragma unroll
                for (int t = 0; t < 4; t++) sacc[ng][nt][t] = 0.f;

        uint32_t kaH = smem_u32(&QKh[(lane & 15) * FA_ST + (lane >> 4) * 8]);
        uint32_t kaL = smem_u32(&QKl[(lane & 15) * FA_ST + (lane >> 4) * 8]);
        #pragma unroll
        for (int ng = 0; ng < 8; ng++) {
            #pragma unroll
            for (int d = 0; d < 4; d++) {
                uint32_t kbh[4], kbl[4];
                ldsm4(kaH + (uint32_t)(ng * 16 * FA_ST * 2) + d * 32, kbh);
                ldsm4(kaL + (uint32_t)(ng * 16 * FA_ST * 2) + d * 32, kbl);
                uint32_t b0h[2] = {kbh[0], kbh[2]}, b1h[2] = {kbh[1], kbh[3]};
                uint32_t b0l[2] = {kbl[0], kbl[2]}, b1l[2] = {kbl[1], kbl[3]};
                mma16816(sacc[ng][0], qfh[d], b0h);
                mma16816(sacc[ng][0], qfh[d], b0l);
                mma16816(sacc[ng][0], qfl[d], b0h);
                mma16816(sacc[ng][1], qfh[d], b1h);
                mma16816(sacc[ng][1], qfh[d], b1l);
                mma16816(sacc[ng][1], qfl[d], b1h);
            }
        }

        const int rl = w * 16 + (lane >> 2);
        if (kt == qt) {
            #pragma unroll
            for (int ng = 0; ng < 8; ng++)
                #pragma unroll
                for (int nt = 0; nt < 2; nt++) {
                    int cl = ng * 16 + nt * 8 + 2 * (lane & 3);
                    if (cl     > rl)     sacc[ng][nt][0] = -1e30f;
                    if (cl + 1 > rl)     sacc[ng][nt][1] = -1e30f;
                    if (cl     > rl + 8) sacc[ng][nt][2] = -1e30f;
                    if (cl + 1 > rl + 8) sacc[ng][nt][3] = -1e30f;
                }
        }

        float tm0 = -1e30f, tm1 = -1e30f;
        #pragma unroll
        for (int ng = 0; ng < 8; ng++)
            #pragma unroll
            for (int nt = 0; nt < 2; nt++) {
                tm0 = fmaxf(tm0, fmaxf(sacc[ng][nt][0], sacc[ng][nt][1]));
                tm1 = fmaxf(tm1, fmaxf(sacc[ng][nt][2], sacc[ng][nt][3]));
            }
        tm0 = fmaxf(tm0, __shfl_xor_sync(0xffffffffu, tm0, 1));
        tm0 = fmaxf(tm0, __shfl_xor_sync(0xffffffffu, tm0, 2));
        tm1 = fmaxf(tm1, __shfl_xor_sync(0xffffffffu, tm1, 1));
        tm1 = fmaxf(tm1, __shfl_xor_sync(0xffffffffu, tm1, 2));

        float mn0 = fmaxf(m0, tm0), mn1 = fmaxf(m1, tm1);
        float sc0 = __expf(m0 - mn0), sc1 = __expf(m1 - mn1);
        m0 = mn0; m1 = mn1;

        float ts0 = 0.f, ts1 = 0.f;
        #pragma unroll
        for (int ng = 0; ng < 8; ng++)
            #pragma unroll
            for (int nt = 0; nt < 2; nt++) {
                float e0 = __expf(sacc[ng][nt][0] - mn0);
                float e1 = __expf(sacc[ng][nt][1] - mn0);
                float e2 = __expf(sacc[ng][nt][2] - mn1);
                float e3 = __expf(sacc[ng][nt][3] - mn1);
                sacc[ng][nt][0] = e0; sacc[ng][nt][1] = e1;
                sacc[ng][nt][2] = e2; sacc[ng][nt][3] = e3;
                ts0 += e0 + e1; ts1 += e2 + e3;
            }
        ts0 += __shfl_xor_sync(0xffffffffu, ts0, 1);
        ts0 += __shfl_xor_sync(0xffffffffu, ts0, 2);
        ts1 += __shfl_xor_sync(0xffffffffu, ts1, 1);
        ts1 += __shfl_xor_sync(0xffffffffu, ts1, 2);
        l0 = l0 * sc0 + ts0;
        l1 = l1 * sc1 + ts1;
        #pragma unroll
        for (int j = 0; j < 8; j++) {
            oacc[j][0] *= sc0; oacc[j][1] *= sc0;
            oacc[j][2] *= sc1; oacc[j][3] *= sc1;
        }

        uint32_t vaH = smem_u32(&Vh[(lane & 15) * FA_ST]);
        uint32_t vaL = smem_u32(&Vl[(lane & 15) * FA_ST]);
        #pragma unroll
        for (int kc = 0; kc < 8; kc++) {
            uint32_t pah[4], pal[4];
            split_pack(sacc[kc][0][0], sacc[kc][0][1], pah[0], pal[0]);
            split_pack(sacc[kc][0][2], sacc[kc][0][3], pah[1], pal[1]);
            split_pack(sacc[kc][1][0], sacc[kc][1][1], pah[2], pal[2]);
            split_pack(sacc[kc][1][2], sacc[kc][1][3], pah[3], pal[3]);
            #pragma unroll
            for (int nt = 0; nt < 8; nt++) {
                uint32_t vbh[2], vbl[2];
                ldsm2t(vaH + (uint32_t)(kc * 16 * FA_ST * 2) + nt * 16, vbh);
                ldsm2t(vaL + (uint32_t)(kc * 16 * FA_ST * 2) + nt * 16, vbl);
                mma16816(oacc[nt], pah, vbh);
                mma16816(oacc[nt], pah, vbl);
                mma16816(oacc[nt], pal, vbh);
            }
        }
    }

    // epilogue -> bf16 hi/lo
    float inv0 = 1.0f / l0, inv1 = 1.0f / l1;
    int r0 = qt * 128 + w * 16 + (lane >> 2);
    size_t base0 = ((size_t)(b * SEQ) + r0) * DIM + h * DHEAD;
    size_t base1 = base0 + 8 * DIM;
    #pragma unroll
    for (int nt = 0; nt < 8; nt++) {
        int col = nt * 8 + 2 * (lane & 3);
        __nv_bfloat16 h0,h1,l0b,l1b;
        split2(oacc[nt][0] * inv0, h0, l0b);
        split2(oacc[nt][1] * inv0, h1, l1b);
        *(__nv_bfloat162*)(xh + base0 + col) = __nv_bfloat162(h0, h1);
        *(__nv_bfloat162*)(xl + base0 + col) = __nv_bfloat162(l0b, l1b);
        split2(oacc[nt][2] * inv1, h0, l0b);
        split2(oacc[nt][3] * inv1, h1, l1b);
        *(__nv_bfloat162*)(xh + base1 + col) = __nv_bfloat162(h0, h1);
        *(__nv_bfloat162*)(xl + base1 + col) = __nv_bfloat162(l0b, l1b);
    }
}

// ---------------- pure-bf16 hi/lo GEMM, cp.async 3-stage pipeline ----------------
// C = A @ B + bias (+gelu -> bf16 hi/lo | +residual -> fp32). A,B pre-split bf16.
// MODE: 0 = bias -> fp32 C; 1 = bias+gelu -> (Ch,Cl) bf16; 2 = bias+res -> fp32 C.
// GUARD: head GEMM (B padded to VPAD; stores guarded on col<N).
#define AST 40
#define BST 136
#define ABUFE (128*AST)
#define BBUFE (32*BST)
#define STG 3
#define G3_SMEM (STG * (2*ABUFE + 2*BBUFE) * 2)   // 113664 bytes

template <int MODE, bool GUARD>
__global__ __launch_bounds__(256, 1)
void hgemm3_kernel(const __nv_bfloat16* __restrict__ AhG,
                   const __nv_bfloat16* __restrict__ AlG,
                   const __nv_bfloat16* __restrict__ BhG,
                   const __nv_bfloat16* __restrict__ BlG, int ldb,
                   const float* __restrict__ bias, const float* __restrict__ res,
                   float* __restrict__ C,
                   __nv_bfloat16* __restrict__ Ch, __nv_bfloat16* __restrict__ Cl,
                   int M, int N, int K) {
    extern __shared__ __nv_bfloat16 sm[];
    __nv_bfloat16* Ah = sm;                          // [STG][ABUFE]
    __nv_bfloat16* Al = sm + STG*ABUFE;
    __nv_bfloat16* Bh = sm + 2*STG*ABUFE;            // [STG][BBUFE]
    __nv_bfloat16* Bl = sm + 2*STG*ABUFE + STG*BBUFE;

    const int tid = threadIdx.x, lane = tid & 31, warp = tid >> 5;
    const int warpM = warp >> 2, warpN = warp & 3;
    const int mBase = blockIdx.y * 128, nBase = blockIdx.x * 128;

    // cp.async maps: A tile 128x32 (4 chunks/row), B tile 32x128 (16 chunks/row)
    int arow[2], achk[2], brow[2], bcol[2];
    #pragma unroll
    for (int i = 0; i < 2; i++) {
        int idx = i * 256 + tid;
        arow[i] = idx >> 2;  achk[i] = (idx & 3) * 8;
        brow[i] = idx >> 4;  bcol[i] = (idx & 15) * 8;
    }

    const uint32_t ahS = smem_u32(Ah), alS = smem_u32(Al);
    const uint32_t bhS = smem_u32(Bh), blS = smem_u32(Bl);

    auto issue = [&](int k0, int s) {
        #pragma unroll
        for (int i = 0; i < 2; i++) {
            size_t ga = (size_t)(mBase + arow[i]) * K + k0 + achk[i];
            uint32_t sa = (uint32_t)(s * ABUFE + arow[i] * AST + achk[i]) * 2;
            cpasync16(ahS + sa, AhG + ga);
            cpasync16(alS + sa, AlG + ga);
            size_t gb = (size_t)(k0 + brow[i]) * ldb + nBase + bcol[i];
            uint32_t sb = (uint32_t)(s * BBUFE + brow[i] * BST + bcol[i]) * 2;
            cpasync16(bhS + sb, BhG + gb);
            cpasync16(blS + sb, BlG + gb);
        }
    };

    float acc[4][4][4];
    #pragma unroll
    for (int mi = 0; mi < 4; mi++)
        #pragma unroll
        for (int ni = 0; ni < 4; ni++)
            #pragma unroll
            for (int t = 0; t < 4; t++) acc[mi][ni][t] = 0.f;

    const uint32_t aAddrH = smem_u32(&Ah[(warpM*64 + (lane & 15)) * AST + (lane >> 4) * 8]);
    const uint32_t aAddrL = smem_u32(&Al[(warpM*64 + (lane & 15)) * AST + (lane >> 4) * 8]);
    const uint32_t bAddrH = smem_u32(&Bh[(lane & 15) * BST + warpN * 32]);
    const uint32_t bAddrL = smem_u32(&Bl[(lane & 15) * BST + warpN * 32]);

    const int nchunk = K >> 5;
    // prologue: stages 0,1
    issue(0, 0); cpasync_commit();
    issue(32, 1); cpasync_commit();

    for (int it = 0; it < nchunk; it++) {
        cpasync_wait1();        // chunk `it` landed (pending <= 1 newest group)
        __syncthreads();        // all warps see it; bounds skew for stage reuse

        const int s = it % STG;
        const uint32_t aOff = (uint32_t)(s * ABUFE) * 2;
        const uint32_t bOff = (uint32_t)(s * BBUFE) * 2;
        #pragma unroll
        for (int ks = 0; ks < 2; ks++) {
            uint32_t afh[4][4], afl[4][4], bfh[4][2], bfl[4][2];
            #pragma unroll
            for (int mi = 0; mi < 4; mi++) {
                uint32_t off = aOff + (uint32_t)(mi * 16 * AST + ks * 16) * 2;
                ldsm4(aAddrH + off, afh[mi]);
                ldsm4(aAddrL + off, afl[mi]);
            }
            #pragma unroll
            for (int ni = 0; ni < 4; ni++) {
                uint32_t off = bOff + (uint32_t)(ks * 16 * BST + ni * 8) * 2;
                ldsm2t(bAddrH + off, bfh[ni]);
                ldsm2t(bAddrL + off, bfl[ni]);
            }
            #pragma unroll
            for (int mi = 0; mi < 4; mi++)
                #pragma unroll
                for (int ni = 0; ni < 4; ni++) {
                    mma16816(acc[mi][ni], afh[mi], bfh[ni]);
                    mma16816(acc[mi][ni], afh[mi], bfl[ni]);
                    mma16816(acc[mi][ni], afl[mi], bfh[ni]);
                }
        }

        // issue chunk it+2 into stage (it+2)%3 — safe: all warps passed the barrier,
        // so none is still reading that stage (it-1's readers are done).
        int nk = it + STG - 1;
        if (nk < nchunk) issue(nk * 32, nk % STG);
        cpasync_commit();       // empty group on tail keeps wait counts aligned
    }

    // epilogue
    const int gr = lane >> 2, gc = (lane & 3) * 2;
    #pragma unroll
    for (int mi = 0; mi < 4; mi++) {
        int r0 = mBase + warpM * 64 + mi * 16 + gr;
        #pragma unroll
        for (int ni = 0; ni < 4; ni++) {
            int col = nBase + warpN * 32 + ni * 8 + gc;
            if (GUARD && col >= N) continue;
            float b0 = bias[col], b1 = bias[col + 1];
            float v0 = acc[mi][ni][0] + b0, v1 = acc[mi][ni][1] + b1;
            float v2 = acc[mi][ni][2] + b0, v3 = acc[mi][ni][3] + b1;
            if (MODE == 1) {
                v0 = gelu_f(v0); v1 = gelu_f(v1); v2 = gelu_f(v2); v3 = gelu_f(v3);
                __nv_bfloat16 h0,h1,l0,l1;
                split2(v0,h0,l0); split2(v1,h1,l1);
                *(__nv_bfloat162*)(Ch + (size_t)r0 * N + col) = __nv_bfloat162(h0,h1);
                *(__nv_bfloat162*)(Cl + (size_t)r0 * N + col) = __nv_bfloat162(l0,l1);
                split2(v2,h0,l0); split2(v3,h1,l1);
                *(__nv_bfloat162*)(Ch + (size_t)(r0+8) * N + col) = __nv_bfloat162(h0,h1);
                *(__nv_bfloat162*)(Cl + (size_t)(r0+8) * N + col) = __nv_bfloat162(l0,l1);
            } else {
                if (MODE == 2) {
                    const float* rr0 = res + (size_t)r0 * N + col;
                    const float* rr1 = res + (size_t)(r0 + 8) * N + col;
                    v0 += rr0[0]; v1 += rr0[1]; v2 += rr1[0]; v3 += rr1[1];
                }
                *(float2*)(C + (size_t)r0 * N + col)       = make_float2(v0, v1);
                *(float2*)(C + (size_t)(r0 + 8) * N + col) = make_float2(v2, v3);
            }
        }
    }
}

// ---------------- launch ----------------
extern "C" void kernel_launch(void* const* d_in, const int* in_sizes, int n_in,
                              void* d_out, int out_size) {
    const int*   input_ids = (const int*)  d_in[0];
    const int*   type_ids  = (const int*)  d_in[1];
    const float* wte    = (const float*)d_in[2];
    const float* wtte   = (const float*)d_in[3];
    const float* wpe    = (const float*)d_in[4];
    const float* ln1_w  = (const float*)d_in[5];
    const float* ln1_b  = (const float*)d_in[6];
    const float* attn_w = (const float*)d_in[7];
    const float* attn_b = (const float*)d_in[8];
    const float* atp_w  = (const float*)d_in[9];
    const float* atp_b  = (const float*)d_in[10];
    const float* ln2_w  = (const float*)d_in[11];
    const float* ln2_b  = (const float*)d_in[12];
    const float* fc_w   = (const float*)d_in[13];
    const float* fc_b   = (const float*)d_in[14];
    const float* mlp_w  = (const float*)d_in[15];
    const float* mlp_b  = (const float*)d_in[16];
    const float* lnf_w  = (const float*)d_in[17];
    const float* lnf_b  = (const float*)d_in[18];
    const float* head_w = (const float*)d_in[19];
    const float* head_b = (const float*)d_in[20];
    float* out = (float*)d_out;

    float *h, *qkv;
    __nv_bfloat16 *xh, *xl, *mh, *ml;
    cudaGetSymbolAddress((void**)&h,   g_h);
    cudaGetSymbolAddress((void**)&qkv, g_qkv);
    cudaGetSymbolAddress((void**)&xh,  g_xh);  cudaGetSymbolAddress((void**)&xl, g_xl);
    cudaGetSymbolAddress((void**)&mh,  g_mh);  cudaGetSymbolAddress((void**)&ml, g_ml);

    __nv_bfloat16 *wqh, *wql, *wph, *wpl, *wfh, *wfl, *wmh, *wml, *whh, *whl;
    cudaGetSymbolAddress((void**)&wqh, g_wqkv_h); cudaGetSymbolAddress((void**)&wql, g_wqkv_l);
    cudaGetSymbolAddress((void**)&wph, g_watp_h); cudaGetSymbolAddress((void**)&wpl, g_watp_l);
    cudaGetSymbolAddress((void**)&wfh, g_wfc_h);  cudaGetSymbolAddress((void**)&wfl, g_wfc_l);
    cudaGetSymbolAddress((void**)&wmh, g_wmlp_h); cudaGetSymbolAddress((void**)&wml, g_wmlp_l);
    cudaGetSymbolAddress((void**)&whh, g_whead_h); cudaGetSymbolAddress((void**)&whl, g_whead_l);

    const int FA_SMEM = 4 * FA_TILE * (int)sizeof(__nv_bfloat16);
    cudaFuncSetAttribute(flash_attn_kernel,
                         cudaFuncAttributeMaxDynamicSharedMemorySize, FA_SMEM);
    cudaFuncSetAttribute(hgemm3_kernel<0, false>,
                         cudaFuncAttributeMaxDynamicSharedMemorySize, G3_SMEM);
    cudaFuncSetAttribute(hgemm3_kernel<1, false>,
                         cudaFuncAttributeMaxDynamicSharedMemorySize, G3_SMEM);
    cudaFuncSetAttribute(hgemm3_kernel<2, false>,
                         cudaFuncAttributeMaxDynamicSharedMemorySize, G3_SMEM);
    cudaFuncSetAttribute(hgemm3_kernel<0, true>,
                         cudaFuncAttributeMaxDynamicSharedMemorySize, G3_SMEM);

    // ---- pre-split weights ----
    {
        int n4;
        n4 = NLAYER * DIM * 3 * DIM / 4;
        wsplit_kernel<<<(n4 + 255) / 256, 256>>>(attn_w, wqh, wql, n4);
        n4 = NLAYER * DIM * DIM / 4;
        wsplit_kernel<<<(n4 + 255) / 256, 256>>>(atp_w, wph, wpl, n4);
        n4 = NLAYER * DIM * 4 * DIM / 4;
        wsplit_kernel<<<(n4 + 255) / 256, 256>>>(fc_w, wfh, wfl, n4);
        n4 = NLAYER * 4 * DIM * DIM / 4;
        wsplit_kernel<<<(n4 + 255) / 256, 256>>>(mlp_w, wmh, wml, n4);
        wsplit_head_kernel<<<dim3((VPAD + 255) / 256, DIM), 256>>>(head_w, whh, whl);
    }

    embed_kernel<<<MTOK, 256>>>(input_ids, type_ids, wte, wtte, wpe, h);

    for (int l = 0; l < NLAYER; l++) {
        const __nv_bfloat16* awh = wqh + (size_t)l * DIM * 3 * DIM;
        const __nv_bfloat16* awl = wql + (size_t)l * DIM * 3 * DIM;
        const __nv_bfloat16* pwh = wph + (size_t)l * DIM * DIM;
        const __nv_bfloat16* pwl = wpl + (size_t)l * DIM * DIM;
        const __nv_bfloat16* fwh = wfh + (size_t)l * DIM * 4 * DIM;
        const __nv_bfloat16* fwl = wfl + (size_t)l * DIM * 4 * DIM;
        const __nv_bfloat16* mwh = wmh + (size_t)l * 4 * DIM * DIM;
        const __nv_bfloat16* mwl = wml + (size_t)l * 4 * DIM * DIM;
        const float* ab = attn_b + (size_t)l * 3 * DIM;
        const float* pb = atp_b  + (size_t)l * DIM;
        const float* fb = fc_b   + (size_t)l * 4 * DIM;
        const float* mb = mlp_b  + (size_t)l * DIM;

        ln_bf_kernel<<<MTOK, 256>>>(h, xh, xl, ln1_w + l * DIM, ln1_b + l * DIM);
        hgemm3_kernel<0, false><<<dim3(3 * DIM / 128, MTOK / 128), 256, G3_SMEM>>>(
            xh, xl, awh, awl, 3 * DIM, ab, nullptr, qkv, nullptr, nullptr, MTOK, 3 * DIM, DIM);
        flash_attn_kernel<<<dim3(NQT, NHEAD, BATCH), 256, FA_SMEM>>>(qkv, xh, xl);
        hgemm3_kernel<2, false><<<dim3(DIM / 128, MTOK / 128), 256, G3_SMEM>>>(
            xh, xl, pwh, pwl, DIM, pb, h, h, nullptr, nullptr, MTOK, DIM, DIM);
        ln_bf_kernel<<<MTOK, 256>>>(h, xh, xl, ln2_w + l * DIM, ln2_b + l * DIM);
        hgemm3_kernel<1, false><<<dim3(4 * DIM / 128, MTOK / 128), 256, G3_SMEM>>>(
            xh, xl, fwh, fwl, 4 * DIM, fb, nullptr, nullptr, mh, ml, MTOK, 4 * DIM, DIM);
        hgemm3_kernel<2, false><<<dim3(DIM / 128, MTOK / 128), 256, G3_SMEM>>>(
            mh, ml, mwh, mwl, DIM, mb, h, h, nullptr, nullptr, MTOK, DIM, 4 * DIM);
    }

    ln_bf_kernel<<<MTOK, 256>>>(h, xh, xl, lnf_w, lnf_b);
    hgemm3_kernel<0, true><<<dim3(VPAD / 128, MTOK / 128), 256, G3_SMEM>>>(
        xh, xl, whh, whl, VPAD, head_b, nullptr, out, nullptr, nullptr, MTOK, VOCAB, DIM);
}

// round 14
// speedup vs baseline: 1.0002x; 1.0002x over previous
#include <cuda_runtime.h>
#include <cuda_bf16.h>
#include <math.h>
#include <stdint.h>

// ---------------- problem constants ----------------
#define SEQ   512
#define DIM   1024
#define NHEAD 16
#define DHEAD 64
#define BATCH 4
#define VOCAB 16386
#define VPAD  16512        // 129 * 128
#define NLAYER 12
#define MTOK  (BATCH*SEQ)   // 2048
#define NQT   (SEQ/128)     // 4 q-tiles

// ---------------- scratch (device globals; no allocation) ----------------
__device__ float g_h[MTOK*DIM];                                  // residual (fp32)
__device__ float g_qkv[MTOK*3*DIM];                              // qkv (fp32, attn input)
__device__ __nv_bfloat16 g_xh[MTOK*DIM],   g_xl[MTOK*DIM];       // activation hi/lo
__device__ __nv_bfloat16 g_mh[MTOK*4*DIM], g_ml[MTOK*4*DIM];     // mlp mid hi/lo

// pre-split bf16 hi/lo weights (written every launch)
__device__ __nv_bfloat16 g_wqkv_h[NLAYER*DIM*3*DIM], g_wqkv_l[NLAYER*DIM*3*DIM];
__device__ __nv_bfloat16 g_watp_h[NLAYER*DIM*DIM],   g_watp_l[NLAYER*DIM*DIM];
__device__ __nv_bfloat16 g_wfc_h [NLAYER*DIM*4*DIM], g_wfc_l [NLAYER*DIM*4*DIM];
__device__ __nv_bfloat16 g_wmlp_h[NLAYER*4*DIM*DIM], g_wmlp_l[NLAYER*4*DIM*DIM];
__device__ __nv_bfloat16 g_whead_h[DIM*VPAD],        g_whead_l[DIM*VPAD];

// ---------------- split helpers ----------------
__device__ __forceinline__ void split2(float a, __nv_bfloat16& hi, __nv_bfloat16& lo) {
    hi = __float2bfloat16(a);
    lo = __float2bfloat16(a - __bfloat162float(hi));
}
__device__ __forceinline__ void split_pack(float a, float b, uint32_t& hi, uint32_t& lo) {
    __nv_bfloat16 ah, al, bh, bl;
    split2(a, ah, al); split2(b, bh, bl);
    __nv_bfloat162 H(ah, bh), L(al, bl);
    hi = *(uint32_t*)&H; lo = *(uint32_t*)&L;
}

// ---------------- weight pre-split kernels ----------------
__global__ void wsplit_kernel(const float* __restrict__ w,
                              __nv_bfloat16* __restrict__ hi,
                              __nv_bfloat16* __restrict__ lo, int n4) {
    int i = blockIdx.x * blockDim.x + threadIdx.x;
    if (i >= n4) return;
    float4 v = ((const float4*)w)[i];
    __nv_bfloat16 h0,h1,h2,h3,l0,l1,l2,l3;
    split2(v.x,h0,l0); split2(v.y,h1,l1); split2(v.z,h2,l2); split2(v.w,h3,l3);
    __nv_bfloat162* ph = (__nv_bfloat162*)hi + 2*i;
    __nv_bfloat162* pl = (__nv_bfloat162*)lo + 2*i;
    ph[0] = __nv_bfloat162(h0,h1); ph[1] = __nv_bfloat162(h2,h3);
    pl[0] = __nv_bfloat162(l0,l1); pl[1] = __nv_bfloat162(l2,l3);
}
__global__ void wsplit_head_kernel(const float* __restrict__ w,
                                   __nv_bfloat16* __restrict__ hi,
                                   __nv_bfloat16* __restrict__ lo) {
    int col = blockIdx.x * blockDim.x + threadIdx.x;
    int row = blockIdx.y;
    if (col >= VPAD) return;
    float v = (col < VOCAB) ? w[(size_t)row * VOCAB + col] : 0.f;
    __nv_bfloat16 h, l; split2(v, h, l);
    hi[(size_t)row * VPAD + col] = h;
    lo[(size_t)row * VPAD + col] = l;
}

// ---------------- embedding ----------------
__global__ void embed_kernel(const int* __restrict__ ids, const int* __restrict__ tts,
                             const float* __restrict__ wte, const float* __restrict__ wtte,
                             const float* __restrict__ wpe, float* __restrict__ out) {
    int row = blockIdx.x;
    int s   = row & (SEQ - 1);
    int id  = ids[row];
    int tt  = tts[row];
    const float4* te = (const float4*)(wte  + (size_t)id * DIM);
    const float4* ty = (const float4*)(wtte + (size_t)tt * DIM);
    const float4* pe = (const float4*)(wpe  + (size_t)s  * DIM);
    float4* o = (float4*)(out + (size_t)row * DIM);
    int i = threadIdx.x;
    float4 a = te[i], b = ty[i], c = pe[i];
    o[i] = make_float4(a.x + b.x + c.x, a.y + b.y + c.y,
                       a.z + b.z + c.z, a.w + b.w + c.w);
}

// ---------------- block reduction helper (256 threads) ----------------
__device__ __forceinline__ float blockSum256(float v, float* red) {
    #pragma unroll
    for (int o = 16; o > 0; o >>= 1) v += __shfl_xor_sync(0xffffffffu, v, o);
    if ((threadIdx.x & 31) == 0) red[threadIdx.x >> 5] = v;
    __syncthreads();
    if (threadIdx.x == 0) {
        float t = 0.f;
        #pragma unroll
        for (int i = 0; i < 8; i++) t += red[i];
        red[0] = t;
    }
    __syncthreads();
    float r = red[0];
    __syncthreads();
    return r;
}

// ---------------- layernorm -> bf16 hi/lo ----------------
__global__ void ln_bf_kernel(const float* __restrict__ in,
                             __nv_bfloat16* __restrict__ oh, __nv_bfloat16* __restrict__ ol,
                             const float* __restrict__ w, const float* __restrict__ b) {
    __shared__ float red[8];
    int row = blockIdx.x;
    int t = threadIdx.x;
    const float4* ip = (const float4*)(in + (size_t)row * DIM);
    float4 v = ip[t];
    float s  = v.x + v.y + v.z + v.w;
    float sq = v.x*v.x + v.y*v.y + v.z*v.z + v.w*v.w;
    float tot  = blockSum256(s,  red);
    float tot2 = blockSum256(sq, red);
    float mean = tot * (1.0f / DIM);
    float var  = tot2 * (1.0f / DIM) - mean * mean;
    float rstd = rsqrtf(var + 1e-5f);
    const float4 w4 = ((const float4*)w)[t];
    const float4 b4 = ((const float4*)b)[t];
    float o0 = (v.x - mean) * rstd * w4.x + b4.x;
    float o1 = (v.y - mean) * rstd * w4.y + b4.y;
    float o2 = (v.z - mean) * rstd * w4.z + b4.z;
    float o3 = (v.w - mean) * rstd * w4.w + b4.w;
    __nv_bfloat16 h0,h1,h2,h3,l0,l1,l2,l3;
    split2(o0,h0,l0); split2(o1,h1,l1); split2(o2,h2,l2); split2(o3,h3,l3);
    size_t off = (size_t)row * DIM + t * 4;
    *(__nv_bfloat162*)(oh + off)     = __nv_bfloat162(h0, h1);
    *(__nv_bfloat162*)(oh + off + 2) = __nv_bfloat162(h2, h3);
    *(__nv_bfloat162*)(ol + off)     = __nv_bfloat162(l0, l1);
    *(__nv_bfloat162*)(ol + off + 2) = __nv_bfloat162(l2, l3);
}

// ---------------- GELU ----------------
__device__ __forceinline__ float gelu_f(float x) {
    const float c0 = 0.7978845608028654f;
    const float c1 = 0.044715f;
    float x3 = x * x * x;
    return 0.5f * x * (1.0f + tanhf(c0 * (x + c1 * x3)));
}

// ---------------- tensor-core primitives ----------------
__device__ __forceinline__ uint32_t smem_u32(const void* p) {
    return (uint32_t)__cvta_generic_to_shared(p);
}
__device__ __forceinline__ void ldsm4(uint32_t addr, uint32_t* r) {
    asm volatile("ldmatrix.sync.aligned.m8n8.x4.shared.b16 {%0,%1,%2,%3},[%4];\n"
                 : "=r"(r[0]), "=r"(r[1]), "=r"(r[2]), "=r"(r[3]) : "r"(addr));
}
__device__ __forceinline__ void ldsm2t(uint32_t addr, uint32_t* r) {
    asm volatile("ldmatrix.sync.aligned.m8n8.x2.trans.shared.b16 {%0,%1},[%2];\n"
                 : "=r"(r[0]), "=r"(r[1]) : "r"(addr));
}
__device__ __forceinline__ void mma16816(float* c, const uint32_t* a, const uint32_t* b) {
    asm volatile("mma.sync.aligned.m16n8k16.row.col.f32.bf16.bf16.f32 "
                 "{%0,%1,%2,%3},{%4,%5,%6,%7},{%8,%9},{%0,%1,%2,%3};\n"
                 : "+f"(c[0]), "+f"(c[1]), "+f"(c[2]), "+f"(c[3])
                 : "r"(a[0]), "r"(a[1]), "r"(a[2]), "r"(a[3]), "r"(b[0]), "r"(b[1]));
}
__device__ __forceinline__ void cpasync16(uint32_t dst, const void* src) {
    asm volatile("cp.async.cg.shared.global [%0], [%1], 16;\n" :: "r"(dst), "l"(src));
}
__device__ __forceinline__ void cpasync_commit() {
    asm volatile("cp.async.commit_group;\n");
}
__device__ __forceinline__ void cpasync_wait1() {
    asm volatile("cp.async.wait_group 1;\n");
}

// ---------------- flash attention (bf16 hi/lo output) ----------------
#define FA_ST 72
#define FA_TILE (128*FA_ST)

__device__ __forceinline__ void stage128x64(const float* __restrict__ src,
                                            __nv_bfloat16* sh, __nv_bfloat16* sl,
                                            int tid, float scale) {
    #pragma unroll
    for (int i = 0; i < 8; i++) {
        int idx = i * 256 + tid;
        int row = idx >> 4, c = (idx & 15) * 4;
        float4 v = *(const float4*)(src + (size_t)row * (3 * DIM) + c);
        v.x *= scale; v.y *= scale; v.z *= scale; v.w *= scale;
        __nv_bfloat16 h0, h1, h2, h3, l0, l1, l2, l3;
        split2(v.x, h0, l0); split2(v.y, h1, l1);
        split2(v.z, h2, l2); split2(v.w, h3, l3);
        __nv_bfloat162* ph = (__nv_bfloat162*)&sh[row * FA_ST + c];
        __nv_bfloat162* pl = (__nv_bfloat162*)&sl[row * FA_ST + c];
        ph[0] = __nv_bfloat162(h0, h1); ph[1] = __nv_bfloat162(h2, h3);
        pl[0] = __nv_bfloat162(l0, l1); pl[1] = __nv_bfloat162(l2, l3);
    }
}

__global__ __launch_bounds__(256, 1)
void flash_attn_kernel(const float* __restrict__ qkv,
                       __nv_bfloat16* __restrict__ xh, __nv_bfloat16* __restrict__ xl) {
    extern __shared__ __nv_bfloat16 fasmem[];
    __nv_bfloat16* QKh = fasmem;
    __nv_bfloat16* QKl = fasmem + FA_TILE;
    __nv_bfloat16* Vh  = fasmem + 2 * FA_TILE;
    __nv_bfloat16* Vl  = fasmem + 3 * FA_TILE;

    const int qt = (NQT - 1) - blockIdx.x;
    const int h  = blockIdx.y, b = blockIdx.z;
    const int tid = threadIdx.x, lane = tid & 31, w = tid >> 5;

    const float* qbase = qkv + ((size_t)(b * SEQ + qt * 128)) * (3 * DIM) + h * DHEAD;
    stage128x64(qbase, QKh, QKl, tid, 0.125f);
    __syncthreads();

    uint32_t qfh[4][4], qfl[4][4];
    {
        uint32_t qaH = smem_u32(&QKh[(w * 16 + (lane & 15)) * FA_ST + (lane >> 4) * 8]);
        uint32_t qaL = smem_u32(&QKl[(w * 16 + (lane & 15)) * FA_ST + (lane >> 4) * 8]);
        #pragma unroll
        for (int d = 0; d < 4; d++) { ldsm4(qaH + d * 32, qfh[d]); ldsm4(qaL + d * 32, qfl[d]); }
    }

    float m0 = -1e30f, m1 = -1e30f, l0 = 0.f, l1 = 0.f;
    float oacc[8][4];
    #pragma unroll
    for (int j = 0; j < 8; j++)
        #pragma unroll
        for (int t = 0; t < 4; t++) oacc[j][t] = 0.f;

    const int nkt = qt + 1;
    for (int kt = 0; kt < nkt; kt++) {
        __syncthreads();
        const float* kb = qkv + ((size_t)(b * SEQ + kt * 128)) * (3 * DIM) + DIM + h * DHEAD;
        stage128x64(kb,       QKh, QKl, tid, 1.f);
        stage128x64(kb + DIM, Vh,  Vl,  tid, 1.f);
        __syncthreads();

        float sacc[8][2][4];
        #pragma unroll
        for (int ng = 0; ng < 8; ng++)
            #pragma unroll
            for (int nt = 0; nt < 2; nt++)
                #pragma unroll
                for (int t = 0; t < 4; t++) sacc[ng][nt][t] = 0.f;

        uint32_t kaH = smem_u32(&QKh[(lane & 15) * FA_ST + (lane >> 4) * 8]);
        uint32_t kaL = smem_u32(&QKl[(lane & 15) * FA_ST + (lane >> 4) * 8]);
        #pragma unroll
        for (int ng = 0; ng < 8; ng++) {
            #pragma unroll
            for (int d = 0; d < 4; d++) {
                uint32_t kbh[4], kbl[4];
                ldsm4(kaH + (uint32_t)(ng * 16 * FA_ST * 2) + d * 32, kbh);
                ldsm4(kaL + (uint32_t)(ng * 16 * FA_ST * 2) + d * 32, kbl);
                uint32_t b0h[2] = {kbh[0], kbh[2]}, b1h[2] = {kbh[1], kbh[3]};
                uint32_t b0l[2] = {kbl[0], kbl[2]}, b1l[2] = {kbl[1], kbl[3]};
                mma16816(sacc[ng][0], qfh[d], b0h);
                mma16816(sacc[ng][0], qfh[d], b0l);
                mma16816(sacc[ng][0], qfl[d], b0h);
                mma16816(sacc[ng][1], qfh[d], b1h);
                mma16816(sacc[ng][1], qfh[d], b1l);
                mma16816(sacc[ng][1], qfl[d], b1h);
            }
        }

        const int rl = w * 16 + (lane >> 2);
        if (kt == qt) {
            #pragma unroll
            for (int ng = 0; ng < 8; ng++)
                #pragma unroll
                for (int nt = 0; nt < 2; nt++) {
                    int cl = ng * 16 + nt * 8 + 2 * (lane & 3);
                    if (cl     > rl)     sacc[ng][nt][0] = -1e30f;
                    if (cl + 1 > rl)     sacc[ng][nt][1] = -1e30f;
                    if (cl     > rl + 8) sacc[ng][nt][2] = -1e30f;
                    if (cl + 1 > rl + 8) sacc[ng][nt][3] = -1e30f;
                }
        }

        float tm0 = -1e30f, tm1 = -1e30f;
        #pragma unroll
        for (int ng = 0; ng < 8; ng++)
            #pragma unroll
            for (int nt = 0; nt < 2; nt++) {
                tm0 = fmaxf(tm0, fmaxf(sacc[ng][nt][0], sacc[ng][nt][1]));
                tm1 = fmaxf(tm1, fmaxf(sacc[ng][nt][2], sacc[ng][nt][3]));
            }
        tm0 = fmaxf(tm0, __shfl_xor_sync(0xffffffffu, tm0, 1));
        tm0 = fmaxf(tm0, __shfl_xor_sync(0xffffffffu, tm0, 2));
        tm1 = fmaxf(tm1, __shfl_xor_sync(0xffffffffu, tm1, 1));
        tm1 = fmaxf(tm1, __shfl_xor_sync(0xffffffffu, tm1, 2));

        float mn0 = fmaxf(m0, tm0), mn1 = fmaxf(m1, tm1);
        float sc0 = __expf(m0 - mn0), sc1 = __expf(m1 - mn1);
        m0 = mn0; m1 = mn1;

        float ts0 = 0.f, ts1 = 0.f;
        #pragma unroll
        for (int ng = 0; ng < 8; ng++)
            #pragma unroll
            for (int nt = 0; nt < 2; nt++) {
                float e0 = __expf(sacc[ng][nt][0] - mn0);
                float e1 = __expf(sacc[ng][nt][1] - mn0);
                float e2 = __expf(sacc[ng][nt][2] - mn1);
                float e3 = __expf(sacc[ng][nt][3] - mn1);
                sacc[ng][nt][0] = e0; sacc[ng][nt][1] = e1;
                sacc[ng][nt][2] = e2; sacc[ng][nt][3] = e3;
                ts0 += e0 + e1; ts1 += e2 + e3;
            }
        ts0 += __shfl_xor_sync(0xffffffffu, ts0, 1);
        ts0 += __shfl_xor_sync(0xffffffffu, ts0, 2);
        ts1 += __shfl_xor_sync(0xffffffffu, ts1, 1);
        ts1 += __shfl_xor_sync(0xffffffffu, ts1, 2);
        l0 = l0 * sc0 + ts0;
        l1 = l1 * sc1 + ts1;
        #pragma unroll
        for (int j = 0; j < 8; j++) {
            oacc[j][0] *= sc0; oacc[j][1] *= sc0;
            oacc[j][2] *= sc1; oacc[j][3] *= sc1;
        }

        uint32_t vaH = smem_u32(&Vh[(lane & 15) * FA_ST]);
        uint32_t vaL = smem_u32(&Vl[(lane & 15) * FA_ST]);
        #pragma unroll
        for (int kc = 0; kc < 8; kc++) {
            uint32_t pah[4], pal[4];
            split_pack(sacc[kc][0][0], sacc[kc][0][1], pah[0], pal[0]);
            split_pack(sacc[kc][0][2], sacc[kc][0][3], pah[1], pal[1]);
            split_pack(sacc[kc][1][0], sacc[kc][1][1], pah[2], pal[2]);
            split_pack(sacc[kc][1][2], sacc[kc][1][3], pah[3], pal[3]);
            #pragma unroll
            for (int nt = 0; nt < 8; nt++) {
                uint32_t vbh[2], vbl[2];
                ldsm2t(vaH + (uint32_t)(kc * 16 * FA_ST * 2) + nt * 16, vbh);
                ldsm2t(vaL + (uint32_t)(kc * 16 * FA_ST * 2) + nt * 16, vbl);
                mma16816(oacc[nt], pah, vbh);
                mma16816(oacc[nt], pah, vbl);
                mma16816(oacc[nt], pal, vbh);
            }
        }
    }

    // epilogue -> bf16 hi/lo
    float inv0 = 1.0f / l0, inv1 = 1.0f / l1;
    int r0 = qt * 128 + w * 16 + (lane >> 2);
    size_t base0 = ((size_t)(b * SEQ) + r0) * DIM + h * DHEAD;
    size_t base1 = base0 + 8 * DIM;
    #pragma unroll
    for (int nt = 0; nt < 8; nt++) {
        int col = nt * 8 + 2 * (lane & 3);
        __nv_bfloat16 h0,h1,l0b,l1b;
        split2(oacc[nt][0] * inv0, h0, l0b);
        split2(oacc[nt][1] * inv0, h1, l1b);
        *(__nv_bfloat162*)(xh + base0 + col) = __nv_bfloat162(h0, h1);
        *(__nv_bfloat162*)(xl + base0 + col) = __nv_bfloat162(l0b, l1b);
        split2(oacc[nt][2] * inv1, h0, l0b);
        split2(oacc[nt][3] * inv1, h1, l1b);
        *(__nv_bfloat162*)(xh + base1 + col) = __nv_bfloat162(h0, h1);
        *(__nv_bfloat162*)(xl + base1 + col) = __nv_bfloat162(l0b, l1b);
    }
}

// ---------------- pure-bf16 hi/lo GEMM, cp.async 3-stage pipeline ----------------
// C = A @ B + bias (+gelu -> bf16 hi/lo | +residual -> fp32). A,B pre-split bf16.
// MODE: 0 = bias -> fp32 C; 1 = bias+gelu -> (Ch,Cl) bf16; 2 = bias+res -> fp32 C.
// GUARD: head GEMM (B padded to VPAD; stores guarded on col<N).
#define AST 40
#define BST 136
#define ABUFE (128*AST)
#define BBUFE (32*BST)
#define STG 3
#define G3_SMEM (STG * (2*ABUFE + 2*BBUFE) * 2)   // 113664 bytes

template <int MODE, bool GUARD>
__global__ __launch_bounds__(256, 1)
void hgemm3_kernel(const __nv_bfloat16* __restrict__ AhG,
                   const __nv_bfloat16* __restrict__ AlG,
                   const __nv_bfloat16* __restrict__ BhG,
                   const __nv_bfloat16* __restrict__ BlG, int ldb,
                   const float* __restrict__ bias, const float* __restrict__ res,
                   float* __restrict__ C,
                   __nv_bfloat16* __restrict__ Ch, __nv_bfloat16* __restrict__ Cl,
                   int M, int N, int K) {
    extern __shared__ __nv_bfloat16 sm[];
    __nv_bfloat16* Ah = sm;                          // [STG][ABUFE]
    __nv_bfloat16* Al = sm + STG*ABUFE;
    __nv_bfloat16* Bh = sm + 2*STG*ABUFE;            // [STG][BBUFE]
    __nv_bfloat16* Bl = sm + 2*STG*ABUFE + STG*BBUFE;

    const int tid = threadIdx.x, lane = tid & 31, warp = tid >> 5;
    const int warpM = warp >> 2, warpN = warp & 3;
    const int mBase = blockIdx.y * 128, nBase = blockIdx.x * 128;

    // cp.async maps: A tile 128x32 (4 chunks/row), B tile 32x128 (16 chunks/row)
    int arow[2], achk[2], brow[2], bcol[2];
    #pragma unroll
    for (int i = 0; i < 2; i++) {
        int idx = i * 256 + tid;
        arow[i] = idx >> 2;  achk[i] = (idx & 3) * 8;
        brow[i] = idx >> 4;  bcol[i] = (idx & 15) * 8;
    }

    const uint32_t ahS = smem_u32(Ah), alS = smem_u32(Al);
    const uint32_t bhS = smem_u32(Bh), blS = smem_u32(Bl);

    auto issue = [&](int k0, int s) {
        #pragma unroll
        for (int i = 0; i < 2; i++) {
            size_t ga = (size_t)(mBase + arow[i]) * K + k0 + achk[i];
            uint32_t sa = (uint32_t)(s * ABUFE + arow[i] * AST + achk[i]) * 2;
            cpasync16(ahS + sa, AhG + ga);
            cpasync16(alS + sa, AlG + ga);
            size_t gb = (size_t)(k0 + brow[i]) * ldb + nBase + bcol[i];
            uint32_t sb = (uint32_t)(s * BBUFE + brow[i] * BST + bcol[i]) * 2;
            cpasync16(bhS + sb, BhG + gb);
            cpasync16(blS + sb, BlG + gb);
        }
    };

    float acc[4][4][4];
    #pragma unroll
    for (int mi = 0; mi < 4; mi++)
        #pragma unroll
        for (int ni = 0; ni < 4; ni++)
            #pragma unroll
            for (int t = 0; t < 4; t++) acc[mi][ni][t] = 0.f;

    const uint32_t aAddrH = smem_u32(&Ah[(warpM*64 + (lane & 15)) * AST + (lane >> 4) * 8]);
    const uint32_t aAddrL = smem_u32(&Al[(warpM*64 + (lane & 15)) * AST + (lane >> 4) * 8]);
    const uint32_t bAddrH = smem_u32(&Bh[(lane & 15) * BST + warpN * 32]);
    const uint32_t bAddrL = smem_u32(&Bl[(lane & 15) * BST + warpN * 32]);

    const int nchunk = K >> 5;
    // prologue: stages 0,1
    issue(0, 0); cpasync_commit();
    issue(32, 1); cpasync_commit();

    for (int it = 0; it < nchunk; it++) {
        cpasync_wait1();        // chunk `it` landed (pending <= 1 newest group)
        __syncthreads();        // all warps see it; bounds skew for stage reuse

        const int s = it % STG;
        const uint32_t aOff = (uint32_t)(s * ABUFE) * 2;
        const uint32_t bOff = (uint32_t)(s * BBUFE) * 2;
        #pragma unroll
        for (int ks = 0; ks < 2; ks++) {
            uint32_t afh[4][4], afl[4][4], bfh[4][2], bfl[4][2];
            #pragma unroll
            for (int mi = 0; mi < 4; mi++) {
                uint32_t off = aOff + (uint32_t)(mi * 16 * AST + ks * 16) * 2;
                ldsm4(aAddrH + off, afh[mi]);
                ldsm4(aAddrL + off, afl[mi]);
            }
            #pragma unroll
            for (int ni = 0; ni < 4; ni++) {
                uint32_t off = bOff + (uint32_t)(ks * 16 * BST + ni * 8) * 2;
                ldsm2t(bAddrH + off, bfh[ni]);
                ldsm2t(bAddrL + off, bfl[ni]);
            }
            #pragma unroll
            for (int mi = 0; mi < 4; mi++)
                #pragma unroll
                for (int ni = 0; ni < 4; ni++) {
                    mma16816(acc[mi][ni], afh[mi], bfh[ni]);
                    mma16816(acc[mi][ni], afh[mi], bfl[ni]);
                    mma16816(acc[mi][ni], afl[mi], bfh[ni]);
                }
        }

        // issue chunk it+2 into stage (it+2)%3 — safe: all warps passed the barrier,
        // so none is still reading that stage (it-1's readers are done).
        int nk = it + STG - 1;
        if (nk < nchunk) issue(nk * 32, nk % STG);
        cpasync_commit();       // empty group on tail keeps wait counts aligned
    }

    // epilogue
    const int gr = lane >> 2, gc = (lane & 3) * 2;
    #pragma unroll
    for (int mi = 0; mi < 4; mi++) {
        int r0 = mBase + warpM * 64 + mi * 16 + gr;
        #pragma unroll
        for (int ni = 0; ni < 4; ni++) {
            int col = nBase + warpN * 32 + ni * 8 + gc;
            if (GUARD && col >= N) continue;
            float b0 = bias[col], b1 = bias[col + 1];
            float v0 = acc[mi][ni][0] + b0, v1 = acc[mi][ni][1] + b1;
            float v2 = acc[mi][ni][2] + b0, v3 = acc[mi][ni][3] + b1;
            if (MODE == 1) {
                v0 = gelu_f(v0); v1 = gelu_f(v1); v2 = gelu_f(v2); v3 = gelu_f(v3);
                __nv_bfloat16 h0,h1,l0,l1;
                split2(v0,h0,l0); split2(v1,h1,l1);
                *(__nv_bfloat162*)(Ch + (size_t)r0 * N + col) = __nv_bfloat162(h0,h1);
                *(__nv_bfloat162*)(Cl + (size_t)r0 * N + col) = __nv_bfloat162(l0,l1);
                split2(v2,h0,l0); split2(v3,h1,l1);
                *(__nv_bfloat162*)(Ch + (size_t)(r0+8) * N + col) = __nv_bfloat162(h0,h1);
                *(__nv_bfloat162*)(Cl + (size_t)(r0+8) * N + col) = __nv_bfloat162(l0,l1);
            } else {
                if (MODE == 2) {
                    const float* rr0 = res + (size_t)r0 * N + col;
                    const float* rr1 = res + (size_t)(r0 + 8) * N + col;
                    v0 += rr0[0]; v1 += rr0[1]; v2 += rr1[0]; v3 += rr1[1];
                }
                *(float2*)(C + (size_t)r0 * N + col)       = make_float2(v0, v1);
                *(float2*)(C + (size_t)(r0 + 8) * N + col) = make_float2(v2, v3);
            }
        }
    }
}

// ---------------- launch ----------------
extern "C" void kernel_launch(void* const* d_in, const int* in_sizes, int n_in,
                              void* d_out, int out_size) {
    const int*   input_ids = (const int*)  d_in[0];
    const int*   type_ids  = (const int*)  d_in[1];
    const float* wte    = (const float*)d_in[2];
    const float* wtte   = (const float*)d_in[3];
    const float* wpe    = (const float*)d_in[4];
    const float* ln1_w  = (const float*)d_in[5];
    const float* ln1_b  = (const float*)d_in[6];
    const float* attn_w = (const float*)d_in[7];
    const float* attn_b = (const float*)d_in[8];
    const float* atp_w  = (const float*)d_in[9];
    const float* atp_b  = (const float*)d_in[10];
    const float* ln2_w  = (const float*)d_in[11];
    const float* ln2_b  = (const float*)d_in[12];
    const float* fc_w   = (const float*)d_in[13];
    const float* fc_b   = (const float*)d_in[14];
    const float* mlp_w  = (const float*)d_in[15];
    const float* mlp_b  = (const float*)d_in[16];
    const float* lnf_w  = (const float*)d_in[17];
    const float* lnf_b  = (const float*)d_in[18];
    const float* head_w = (const float*)d_in[19];
    const float* head_b = (const float*)d_in[20];
    float* out = (float*)d_out;

    float *h, *qkv;
    __nv_bfloat16 *xh, *xl, *mh, *ml;
    cudaGetSymbolAddress((void**)&h,   g_h);
    cudaGetSymbolAddress((void**)&qkv, g_qkv);
    cudaGetSymbolAddress((void**)&xh,  g_xh);  cudaGetSymbolAddress((void**)&xl, g_xl);
    cudaGetSymbolAddress((void**)&mh,  g_mh);  cudaGetSymbolAddress((void**)&ml, g_ml);

    __nv_bfloat16 *wqh, *wql, *wph, *wpl, *wfh, *wfl, *wmh, *wml, *whh, *whl;
    cudaGetSymbolAddress((void**)&wqh, g_wqkv_h); cudaGetSymbolAddress((void**)&wql, g_wqkv_l);
    cudaGetSymbolAddress((void**)&wph, g_watp_h); cudaGetSymbolAddress((void**)&wpl, g_watp_l);
    cudaGetSymbolAddress((void**)&wfh, g_wfc_h);  cudaGetSymbolAddress((void**)&wfl, g_wfc_l);
    cudaGetSymbolAddress((void**)&wmh, g_wmlp_h); cudaGetSymbolAddress((void**)&wml, g_wmlp_l);
    cudaGetSymbolAddress((void**)&whh, g_whead_h); cudaGetSymbolAddress((void**)&whl, g_whead_l);

    const int FA_SMEM = 4 * FA_TILE * (int)sizeof(__nv_bfloat16);
    cudaFuncSetAttribute(flash_attn_kernel,
                         cudaFuncAttributeMaxDynamicSharedMemorySize, FA_SMEM);
    cudaFuncSetAttribute(hgemm3_kernel<0, false>,
                         cudaFuncAttributeMaxDynamicSharedMemorySize, G3_SMEM);
    cudaFuncSetAttribute(hgemm3_kernel<1, false>,
                         cudaFuncAttributeMaxDynamicSharedMemorySize, G3_SMEM);
    cudaFuncSetAttribute(hgemm3_kernel<2, false>,
                         cudaFuncAttributeMaxDynamicSharedMemorySize, G3_SMEM);
    cudaFuncSetAttribute(hgemm3_kernel<0, true>,
                         cudaFuncAttributeMaxDynamicSharedMemorySize, G3_SMEM);

    // ---- pre-split weights ----
    {
        int n4;
        n4 = NLAYER * DIM * 3 * DIM / 4;
        wsplit_kernel<<<(n4 + 255) / 256, 256>>>(attn_w, wqh, wql, n4);
        n4 = NLAYER * DIM * DIM / 4;
        wsplit_kernel<<<(n4 + 255) / 256, 256>>>(atp_w, wph, wpl, n4);
        n4 = NLAYER * DIM * 4 * DIM / 4;
        wsplit_kernel<<<(n4 + 255) / 256, 256>>>(fc_w, wfh, wfl, n4);
        n4 = NLAYER * 4 * DIM * DIM / 4;
        wsplit_kernel<<<(n4 + 255) / 256, 256>>>(mlp_w, wmh, wml, n4);
        wsplit_head_kernel<<<dim3((VPAD + 255) / 256, DIM), 256>>>(head_w, whh, whl);
    }

    embed_kernel<<<MTOK, 256>>>(input_ids, type_ids, wte, wtte, wpe, h);

    for (int l = 0; l < NLAYER; l++) {
        const __nv_bfloat16* awh = wqh + (size_t)l * DIM * 3 * DIM;
        const __nv_bfloat16* awl = wql + (size_t)l * DIM * 3 * DIM;
        const __nv_bfloat16* pwh = wph + (size_t)l * DIM * DIM;
        const __nv_bfloat16* pwl = wpl + (size_t)l * DIM * DIM;
        const __nv_bfloat16* fwh = wfh + (size_t)l * DIM * 4 * DIM;
        const __nv_bfloat16* fwl = wfl + (size_t)l * DIM * 4 * DIM;
        const __nv_bfloat16* mwh = wmh + (size_t)l * 4 * DIM * DIM;
        const __nv_bfloat16* mwl = wml + (size_t)l * 4 * DIM * DIM;
        const float* ab = attn_b + (size_t)l * 3 * DIM;
        const float* pb = atp_b  + (size_t)l * DIM;
        const float* fb = fc_b   + (size_t)l * 4 * DIM;
        const float* mb = mlp_b  + (size_t)l * DIM;

        ln_bf_kernel<<<MTOK, 256>>>(h, xh, xl, ln1_w + l * DIM, ln1_b + l * DIM);
        hgemm3_kernel<0, false><<<dim3(3 * DIM / 128, MTOK / 128), 256, G3_SMEM>>>(
            xh, xl, awh, awl, 3 * DIM, ab, nullptr, qkv, nullptr, nullptr, MTOK, 3 * DIM, DIM);
        flash_attn_kernel<<<dim3(NQT, NHEAD, BATCH), 256, FA_SMEM>>>(qkv, xh, xl);
        hgemm3_kernel<2, false><<<dim3(DIM / 128, MTOK / 128), 256, G3_SMEM>>>(
            xh, xl, pwh, pwl, DIM, pb, h, h, nullptr, nullptr, MTOK, DIM, DIM);
        ln_bf_kernel<<<MTOK, 256>>>(h, xh, xl, ln2_w + l * DIM, ln2_b + l * DIM);
        hgemm3_kernel<1, false><<<dim3(4 * DIM / 128, MTOK / 128), 256, G3_SMEM>>>(
            xh, xl, fwh, fwl, 4 * DIM, fb, nullptr, nullptr, mh, ml, MTOK, 4 * DIM, DIM);
        hgemm3_kernel<2, false><<<dim3(DIM / 128, MTOK / 128), 256, G3_SMEM>>>(
            mh, ml, mwh, mwl, DIM, mb, h, h, nullptr, nullptr, MTOK, DIM, 4 * DIM);
    }

    ln_bf_kernel<<<MTOK, 256>>>(h, xh, xl, lnf_w, lnf_b);
    hgemm3_kernel<0, true><<<dim3(VPAD / 128, MTOK / 128), 256, G3_SMEM>>>(
        xh, xl, whh, whl, VPAD, head_b, nullptr, out, nullptr, nullptr, MTOK, VOCAB, DIM);
}

// round 15
// speedup vs baseline: 1.0010x; 1.0009x over previous
#include <cuda_runtime.h>
#include <cuda_bf16.h>
#include <math.h>
#include <stdint.h>

// ---------------- problem constants ----------------
#define SEQ   512
#define DIM   1024
#define NHEAD 16
#define DHEAD 64
#define BATCH 4
#define VOCAB 16386
#define VPAD  16512        // 129 * 128
#define NLAYER 12
#define MTOK  (BATCH*SEQ)   // 2048
#define NQT   (SEQ/128)     // 4 q-tiles

// ---------------- scratch (device globals; no allocation) ----------------
__device__ float g_h[MTOK*DIM];                                  // residual (fp32)
__device__ float g_qkv[MTOK*3*DIM];                              // qkv (fp32, attn input)
__device__ __nv_bfloat16 g_xh[MTOK*DIM],   g_xl[MTOK*DIM];       // activation hi/lo
__device__ __nv_bfloat16 g_mh[MTOK*4*DIM], g_ml[MTOK*4*DIM];     // mlp mid hi/lo

// pre-split bf16 hi/lo weights (written every launch)
__device__ __nv_bfloat16 g_wqkv_h[NLAYER*DIM*3*DIM], g_wqkv_l[NLAYER*DIM*3*DIM];
__device__ __nv_bfloat16 g_watp_h[NLAYER*DIM*DIM],   g_watp_l[NLAYER*DIM*DIM];
__device__ __nv_bfloat16 g_wfc_h [NLAYER*DIM*4*DIM], g_wfc_l [NLAYER*DIM*4*DIM];
__device__ __nv_bfloat16 g_wmlp_h[NLAYER*4*DIM*DIM], g_wmlp_l[NLAYER*4*DIM*DIM];
__device__ __nv_bfloat16 g_whead_h[DIM*VPAD],        g_whead_l[DIM*VPAD];

// ---------------- split helpers ----------------
__device__ __forceinline__ void split2(float a, __nv_bfloat16& hi, __nv_bfloat16& lo) {
    hi = __float2bfloat16(a);
    lo = __float2bfloat16(a - __bfloat162float(hi));
}
__device__ __forceinline__ void split_pack(float a, float b, uint32_t& hi, uint32_t& lo) {
    __nv_bfloat16 ah, al, bh, bl;
    split2(a, ah, al); split2(b, bh, bl);
    __nv_bfloat162 H(ah, bh), L(al, bl);
    hi = *(uint32_t*)&H; lo = *(uint32_t*)&L;
}

// ---------------- weight pre-split kernels ----------------
__global__ void wsplit_kernel(const float* __restrict__ w,
                              __nv_bfloat16* __restrict__ hi,
                              __nv_bfloat16* __restrict__ lo, int n4) {
    int i = blockIdx.x * blockDim.x + threadIdx.x;
    if (i >= n4) return;
    float4 v = ((const float4*)w)[i];
    __nv_bfloat16 h0,h1,h2,h3,l0,l1,l2,l3;
    split2(v.x,h0,l0); split2(v.y,h1,l1); split2(v.z,h2,l2); split2(v.w,h3,l3);
    __nv_bfloat162* ph = (__nv_bfloat162*)hi + 2*i;
    __nv_bfloat162* pl = (__nv_bfloat162*)lo + 2*i;
    ph[0] = __nv_bfloat162(h0,h1); ph[1] = __nv_bfloat162(h2,h3);
    pl[0] = __nv_bfloat162(l0,l1); pl[1] = __nv_bfloat162(l2,l3);
}
__global__ void wsplit_head_kernel(const float* __restrict__ w,
                                   __nv_bfloat16* __restrict__ hi,
                                   __nv_bfloat16* __restrict__ lo) {
    int col = blockIdx.x * blockDim.x + threadIdx.x;
    int row = blockIdx.y;
    if (col >= VPAD) return;
    float v = (col < VOCAB) ? w[(size_t)row * VOCAB + col] : 0.f;
    __nv_bfloat16 h, l; split2(v, h, l);
    hi[(size_t)row * VPAD + col] = h;
    lo[(size_t)row * VPAD + col] = l;
}

// ---------------- embedding ----------------
__global__ void embed_kernel(const int* __restrict__ ids, const int* __restrict__ tts,
                             const float* __restrict__ wte, const float* __restrict__ wtte,
                             const float* __restrict__ wpe, float* __restrict__ out) {
    int row = blockIdx.x;
    int s   = row & (SEQ - 1);
    int id  = ids[row];
    int tt  = tts[row];
    const float4* te = (const float4*)(wte  + (size_t)id * DIM);
    const float4* ty = (const float4*)(wtte + (size_t)tt * DIM);
    const float4* pe = (const float4*)(wpe  + (size_t)s  * DIM);
    float4* o = (float4*)(out + (size_t)row * DIM);
    int i = threadIdx.x;
    float4 a = te[i], b = ty[i], c = pe[i];
    o[i] = make_float4(a.x + b.x + c.x, a.y + b.y + c.y,
                       a.z + b.z + c.z, a.w + b.w + c.w);
}

// ---------------- block reduction helper (256 threads) ----------------
__device__ __forceinline__ float blockSum256(float v, float* red) {
    #pragma unroll
    for (int o = 16; o > 0; o >>= 1) v += __shfl_xor_sync(0xffffffffu, v, o);
    if ((threadIdx.x & 31) == 0) red[threadIdx.x >> 5] = v;
    __syncthreads();
    if (threadIdx.x == 0) {
        float t = 0.f;
        #pragma unroll
        for (int i = 0; i < 8; i++) t += red[i];
        red[0] = t;
    }
    __syncthreads();
    float r = red[0];
    __syncthreads();
    return r;
}

// ---------------- layernorm -> bf16 hi/lo ----------------
__global__ void ln_bf_kernel(const float* __restrict__ in,
                             __nv_bfloat16* __restrict__ oh, __nv_bfloat16* __restrict__ ol,
                             const float* __restrict__ w, const float* __restrict__ b) {
    __shared__ float red[8];
    int row = blockIdx.x;
    int t = threadIdx.x;
    const float4* ip = (const float4*)(in + (size_t)row * DIM);
    float4 v = ip[t];
    float s  = v.x + v.y + v.z + v.w;
    float sq = v.x*v.x + v.y*v.y + v.z*v.z + v.w*v.w;
    float tot  = blockSum256(s,  red);
    float tot2 = blockSum256(sq, red);
    float mean = tot * (1.0f / DIM);
    float var  = tot2 * (1.0f / DIM) - mean * mean;
    float rstd = rsqrtf(var + 1e-5f);
    const float4 w4 = ((const float4*)w)[t];
    const float4 b4 = ((const float4*)b)[t];
    float o0 = (v.x - mean) * rstd * w4.x + b4.x;
    float o1 = (v.y - mean) * rstd * w4.y + b4.y;
    float o2 = (v.z - mean) * rstd * w4.z + b4.z;
    float o3 = (v.w - mean) * rstd * w4.w + b4.w;
    __nv_bfloat16 h0,h1,h2,h3,l0,l1,l2,l3;
    split2(o0,h0,l0); split2(o1,h1,l1); split2(o2,h2,l2); split2(o3,h3,l3);
    size_t off = (size_t)row * DIM + t * 4;
    *(__nv_bfloat162*)(oh + off)     = __nv_bfloat162(h0, h1);
    *(__nv_bfloat162*)(oh + off + 2) = __nv_bfloat162(h2, h3);
    *(__nv_bfloat162*)(ol + off)     = __nv_bfloat162(l0, l1);
    *(__nv_bfloat162*)(ol + off + 2) = __nv_bfloat162(l2, l3);
}

// ---------------- GELU ----------------
__device__ __forceinline__ float gelu_f(float x) {
    const float c0 = 0.7978845608028654f;
    const float c1 = 0.044715f;
    float x3 = x * x * x;
    return 0.5f * x * (1.0f + tanhf(c0 * (x + c1 * x3)));
}

// ---------------- tensor-core primitives ----------------
__device__ __forceinline__ uint32_t smem_u32(const void* p) {
    return (uint32_t)__cvta_generic_to_shared(p);
}
__device__ __forceinline__ void ldsm4(uint32_t addr, uint32_t* r) {
    asm volatile("ldmatrix.sync.aligned.m8n8.x4.shared.b16 {%0,%1,%2,%3},[%4];\n"
                 : "=r"(r[0]), "=r"(r[1]), "=r"(r[2]), "=r"(r[3]) : "r"(addr));
}
__device__ __forceinline__ void ldsm2t(uint32_t addr, uint32_t* r) {
    asm volatile("ldmatrix.sync.aligned.m8n8.x2.trans.shared.b16 {%0,%1},[%2];\n"
                 : "=r"(r[0]), "=r"(r[1]) : "r"(addr));
}
__device__ __forceinline__ void mma16816(float* c, const uint32_t* a, const uint32_t* b) {
    asm volatile("mma.sync.aligned.m16n8k16.row.col.f32.bf16.bf16.f32 "
                 "{%0,%1,%2,%3},{%4,%5,%6,%7},{%8,%9},{%0,%1,%2,%3};\n"
                 : "+f"(c[0]), "+f"(c[1]), "+f"(c[2]), "+f"(c[3])
                 : "r"(a[0]), "r"(a[1]), "r"(a[2]), "r"(a[3]), "r"(b[0]), "r"(b[1]));
}
__device__ __forceinline__ void cpasync16(uint32_t dst, const void* src) {
    asm volatile("cp.async.cg.shared.global [%0], [%1], 16;\n" :: "r"(dst), "l"(src));
}
__device__ __forceinline__ void cpasync_commit() {
    asm volatile("cp.async.commit_group;\n");
}
__device__ __forceinline__ void cpasync_wait1() {
    asm volatile("cp.async.wait_group 1;\n");
}

// ---------------- flash attention (bf16 hi/lo output) ----------------
#define FA_ST 72
#define FA_TILE (128*FA_ST)

__device__ __forceinline__ void stage128x64(const float* __restrict__ src,
                                            __nv_bfloat16* sh, __nv_bfloat16* sl,
                                            int tid, float scale) {
    #pragma unroll
    for (int i = 0; i < 8; i++) {
        int idx = i * 256 + tid;
        int row = idx >> 4, c = (idx & 15) * 4;
        float4 v = *(const float4*)(src + (size_t)row * (3 * DIM) + c);
        v.x *= scale; v.y *= scale; v.z *= scale; v.w *= scale;
        __nv_bfloat16 h0, h1, h2, h3, l0, l1, l2, l3;
        split2(v.x, h0, l0); split2(v.y, h1, l1);
        split2(v.z, h2, l2); split2(v.w, h3, l3);
        __nv_bfloat162* ph = (__nv_bfloat162*)&sh[row * FA_ST + c];
        __nv_bfloat162* pl = (__nv_bfloat162*)&sl[row * FA_ST + c];
        ph[0] = __nv_bfloat162(h0, h1); ph[1] = __nv_bfloat162(h2, h3);
        pl[0] = __nv_bfloat162(l0, l1); pl[1] = __nv_bfloat162(l2, l3);
    }
}

__global__ __launch_bounds__(256, 1)
void flash_attn_kernel(const float* __restrict__ qkv,
                       __nv_bfloat16* __restrict__ xh, __nv_bfloat16* __restrict__ xl) {
    extern __shared__ __nv_bfloat16 fasmem[];
    __nv_bfloat16* QKh = fasmem;
    __nv_bfloat16* QKl = fasmem + FA_TILE;
    __nv_bfloat16* Vh  = fasmem + 2 * FA_TILE;
    __nv_bfloat16* Vl  = fasmem + 3 * FA_TILE;

    const int qt = (NQT - 1) - blockIdx.x;
    const int h  = blockIdx.y, b = blockIdx.z;
    const int tid = threadIdx.x, lane = tid & 31, w = tid >> 5;

    const float* qbase = qkv + ((size_t)(b * SEQ + qt * 128)) * (3 * DIM) + h * DHEAD;
    stage128x64(qbase, QKh, QKl, tid, 0.125f);
    __syncthreads();

    uint32_t qfh[4][4], qfl[4][4];
    {
        uint32_t qaH = smem_u32(&QKh[(w * 16 + (lane & 15)) * FA_ST + (lane >> 4) * 8]);
        uint32_t qaL = smem_u32(&QKl[(w * 16 + (lane & 15)) * FA_ST + (lane >> 4) * 8]);
        #pragma unroll
        for (int d = 0; d < 4; d++) { ldsm4(qaH + d * 32, qfh[d]); ldsm4(qaL + d * 32, qfl[d]); }
    }

    float m0 = -1e30f, m1 = -1e30f, l0 = 0.f, l1 = 0.f;
    float oacc[8][4];
    #pragma unroll
    for (int j = 0; j < 8; j++)
        #pragma unroll
        for (int t = 0; t < 4; t++) oacc[j][t] = 0.f;

    const int nkt = qt + 1;
    for (int kt = 0; kt < nkt; kt++) {
        __syncthreads();
        const float* kb = qkv + ((size_t)(b * SEQ + kt * 128)) * (3 * DIM) + DIM + h * DHEAD;
        stage128x64(kb,       QKh, QKl, tid, 1.f);
        stage128x64(kb + DIM, Vh,  Vl,  tid, 1.f);
        __syncthreads();

        float sacc[8][2][4];
        #pragma unroll
        for (int ng = 0; ng < 8; ng++)
            #pragma unroll
            for (int nt = 0; nt < 2; nt++)
                #pragma unroll
                for (int t = 0; t < 4; t++) sacc[ng][nt][t] = 0.f;

        uint32_t kaH = smem_u32(&QKh[(lane & 15) * FA_ST + (lane >> 4) * 8]);
        uint32_t kaL = smem_u32(&QKl[(lane & 15) * FA_ST + (lane >> 4) * 8]);
        #pragma unroll
        for (int ng = 0; ng < 8; ng++) {
            #pragma unroll
            for (int d = 0; d < 4; d++) {
                uint32_t kbh[4], kbl[4];
                ldsm4(kaH + (uint32_t)(ng * 16 * FA_ST * 2) + d * 32, kbh);
                ldsm4(kaL + (uint32_t)(ng * 16 * FA_ST * 2) + d * 32, kbl);
                uint32_t b0h[2] = {kbh[0], kbh[2]}, b1h[2] = {kbh[1], kbh[3]};
                uint32_t b0l[2] = {kbl[0], kbl[2]}, b1l[2] = {kbl[1], kbl[3]};
                mma16816(sacc[ng][0], qfh[d], b0h);
                mma16816(sacc[ng][0], qfh[d], b0l);
                mma16816(sacc[ng][0], qfl[d], b0h);
                mma16816(sacc[ng][1], qfh[d], b1h);
                mma16816(sacc[ng][1], qfh[d], b1l);
                mma16816(sacc[ng][1], qfl[d], b1h);
            }
        }

        const int rl = w * 16 + (lane >> 2);
        if (kt == qt) {
            #pragma unroll
            for (int ng = 0; ng < 8; ng++)
                #pragma unroll
                for (int nt = 0; nt < 2; nt++) {
                    int cl = ng * 16 + nt * 8 + 2 * (lane & 3);
                    if (cl     > rl)     sacc[ng][nt][0] = -1e30f;
                    if (cl + 1 > rl)     sacc[ng][nt][1] = -1e30f;
                    if (cl     > rl + 8) sacc[ng][nt][2] = -1e30f;
                    if (cl + 1 > rl + 8) sacc[ng][nt][3] = -1e30f;
                }
        }

        float tm0 = -1e30f, tm1 = -1e30f;
        #pragma unroll
        for (int ng = 0; ng < 8; ng++)
            #pragma unroll
            for (int nt = 0; nt < 2; nt++) {
                tm0 = fmaxf(tm0, fmaxf(sacc[ng][nt][0], sacc[ng][nt][1]));
                tm1 = fmaxf(tm1, fmaxf(sacc[ng][nt][2], sacc[ng][nt][3]));
            }
        tm0 = fmaxf(tm0, __shfl_xor_sync(0xffffffffu, tm0, 1));
        tm0 = fmaxf(tm0, __shfl_xor_sync(0xffffffffu, tm0, 2));
        tm1 = fmaxf(tm1, __shfl_xor_sync(0xffffffffu, tm1, 1));
        tm1 = fmaxf(tm1, __shfl_xor_sync(0xffffffffu, tm1, 2));

        float mn0 = fmaxf(m0, tm0), mn1 = fmaxf(m1, tm1);
        float sc0 = __expf(m0 - mn0), sc1 = __expf(m1 - mn1);
        m0 = mn0; m1 = mn1;

        float ts0 = 0.f, ts1 = 0.f;
        #pragma unroll
        for (int ng = 0; ng < 8; ng++)
            #pragma unroll
            for (int nt = 0; nt < 2; nt++) {
                float e0 = __expf(sacc[ng][nt][0] - mn0);
                float e1 = __expf(sacc[ng][nt][1] - mn0);
                float e2 = __expf(sacc[ng][nt][2] - mn1);
                float e3 = __expf(sacc[ng][nt][3] - mn1);
                sacc[ng][nt][0] = e0; sacc[ng][nt][1] = e1;
                sacc[ng][nt][2] = e2; sacc[ng][nt][3] = e3;
                ts0 += e0 + e1; ts1 += e2 + e3;
            }
        ts0 += __shfl_xor_sync(0xffffffffu, ts0, 1);
        ts0 += __shfl_xor_sync(0xffffffffu, ts0, 2);
        ts1 += __shfl_xor_sync(0xffffffffu, ts1, 1);
        ts1 += __shfl_xor_sync(0xffffffffu, ts1, 2);
        l0 = l0 * sc0 + ts0;
        l1 = l1 * sc1 + ts1;
        #pragma unroll
        for (int j = 0; j < 8; j++) {
            oacc[j][0] *= sc0; oacc[j][1] *= sc0;
            oacc[j][2] *= sc1; oacc[j][3] *= sc1;
        }

        uint32_t vaH = smem_u32(&Vh[(lane & 15) * FA_ST]);
        uint32_t vaL = smem_u32(&Vl[(lane & 15) * FA_ST]);
        #pragma unroll
        for (int kc = 0; kc < 8; kc++) {
            uint32_t pah[4], pal[4];
            split_pack(sacc[kc][0][0], sacc[kc][0][1], pah[0], pal[0]);
            split_pack(sacc[kc][0][2], sacc[kc][0][3], pah[1], pal[1]);
            split_pack(sacc[kc][1][0], sacc[kc][1][1], pah[2], pal[2]);
            split_pack(sacc[kc][1][2], sacc[kc][1][3], pah[3], pal[3]);
            #pragma unroll
            for (int nt = 0; nt < 8; nt++) {
                uint32_t vbh[2], vbl[2];
                ldsm2t(vaH + (uint32_t)(kc * 16 * FA_ST * 2) + nt * 16, vbh);
                ldsm2t(vaL + (uint32_t)(kc * 16 * FA_ST * 2) + nt * 16, vbl);
                mma16816(oacc[nt], pah, vbh);
                mma16816(oacc[nt], pah, vbl);
                mma16816(oacc[nt], pal, vbh);
            }
        }
    }

    // epilogue -> bf16 hi/lo
    float inv0 = 1.0f / l0, inv1 = 1.0f / l1;
    int r0 = qt * 128 + w * 16 + (lane >> 2);
    size_t base0 = ((size_t)(b * SEQ) + r0) * DIM + h * DHEAD;
    size_t base1 = base0 + 8 * DIM;
    #pragma unroll
    for (int nt = 0; nt < 8; nt++) {
        int col = nt * 8 + 2 * (lane & 3);
        __nv_bfloat16 h0,h1,l0b,l1b;
        split2(oacc[nt][0] * inv0, h0, l0b);
        split2(oacc[nt][1] * inv0, h1, l1b);
        *(__nv_bfloat162*)(xh + base0 + col) = __nv_bfloat162(h0, h1);
        *(__nv_bfloat162*)(xl + base0 + col) = __nv_bfloat162(l0b, l1b);
        split2(oacc[nt][2] * inv1, h0, l0b);
        split2(oacc[nt][3] * inv1, h1, l1b);
        *(__nv_bfloat162*)(xh + base1 + col) = __nv_bfloat162(h0, h1);
        *(__nv_bfloat162*)(xl + base1 + col) = __nv_bfloat162(l0b, l1b);
    }
}

// ---------------- pure-bf16 hi/lo GEMM, cp.async 3-stage pipeline ----------------
// C = A @ B + bias (+gelu -> bf16 hi/lo | +residual -> fp32). A,B pre-split bf16.
// MODE: 0 = bias -> fp32 C; 1 = bias+gelu -> (Ch,Cl) bf16; 2 = bias+res -> fp32 C.
// GUARD: head GEMM (B padded to VPAD; stores guarded on col<N).
#define AST 40
#define BST 136
#define ABUFE (128*AST)
#define BBUFE (32*BST)
#define STG 3
#define G3_SMEM (STG * (2*ABUFE + 2*BBUFE) * 2)   // 113664 bytes

template <int MODE, bool GUARD>
__global__ __launch_bounds__(256, 1)
void hgemm3_kernel(const __nv_bfloat16* __restrict__ AhG,
                   const __nv_bfloat16* __restrict__ AlG,
                   const __nv_bfloat16* __restrict__ BhG,
                   const __nv_bfloat16* __restrict__ BlG, int ldb,
                   const float* __restrict__ bias, const float* __restrict__ res,
                   float* __restrict__ C,
                   __nv_bfloat16* __restrict__ Ch, __nv_bfloat16* __restrict__ Cl,
                   int M, int N, int K) {
    extern __shared__ __nv_bfloat16 sm[];
    __nv_bfloat16* Ah = sm;                          // [STG][ABUFE]
    __nv_bfloat16* Al = sm + STG*ABUFE;
    __nv_bfloat16* Bh = sm + 2*STG*ABUFE;            // [STG][BBUFE]
    __nv_bfloat16* Bl = sm + 2*STG*ABUFE + STG*BBUFE;

    const int tid = threadIdx.x, lane = tid & 31, warp = tid >> 5;
    const int warpM = warp >> 2, warpN = warp & 3;
    const int mBase = blockIdx.y * 128, nBase = blockIdx.x * 128;

    // cp.async maps: A tile 128x32 (4 chunks/row), B tile 32x128 (16 chunks/row)
    int arow[2], achk[2], brow[2], bcol[2];
    #pragma unroll
    for (int i = 0; i < 2; i++) {
        int idx = i * 256 + tid;
        arow[i] = idx >> 2;  achk[i] = (idx & 3) * 8;
        brow[i] = idx >> 4;  bcol[i] = (idx & 15) * 8;
    }

    const uint32_t ahS = smem_u32(Ah), alS = smem_u32(Al);
    const uint32_t bhS = smem_u32(Bh), blS = smem_u32(Bl);

    auto issue = [&](int k0, int s) {
        #pragma unroll
        for (int i = 0; i < 2; i++) {
            size_t ga = (size_t)(mBase + arow[i]) * K + k0 + achk[i];
            uint32_t sa = (uint32_t)(s * ABUFE + arow[i] * AST + achk[i]) * 2;
            cpasync16(ahS + sa, AhG + ga);
            cpasync16(alS + sa, AlG + ga);
            size_t gb = (size_t)(k0 + brow[i]) * ldb + nBase + bcol[i];
            uint32_t sb = (uint32_t)(s * BBUFE + brow[i] * BST + bcol[i]) * 2;
            cpasync16(bhS + sb, BhG + gb);
            cpasync16(blS + sb, BlG + gb);
        }
    };

    float acc[4][4][4];
    #pragma unroll
    for (int mi = 0; mi < 4; mi++)
        #pragma unroll
        for (int ni = 0; ni < 4; ni++)
            #pragma unroll
            for (int t = 0; t < 4; t++) acc[mi][ni][t] = 0.f;

    const uint32_t aAddrH = smem_u32(&Ah[(warpM*64 + (lane & 15)) * AST + (lane >> 4) * 8]);
    const uint32_t aAddrL = smem_u32(&Al[(warpM*64 + (lane & 15)) * AST + (lane >> 4) * 8]);
    const uint32_t bAddrH = smem_u32(&Bh[(lane & 15) * BST + warpN * 32]);
    const uint32_t bAddrL = smem_u32(&Bl[(lane & 15) * BST + warpN * 32]);

    const int nchunk = K >> 5;
    // prologue: stages 0,1
    issue(0, 0); cpasync_commit();
    issue(32, 1); cpasync_commit();

    for (int it = 0; it < nchunk; it++) {
        cpasync_wait1();        // chunk `it` landed (pending <= 1 newest group)
        __syncthreads();        // all warps see it; bounds skew for stage reuse

        const int s = it % STG;
        const uint32_t aOff = (uint32_t)(s * ABUFE) * 2;
        const uint32_t bOff = (uint32_t)(s * BBUFE) * 2;
        #pragma unroll
        for (int ks = 0; ks < 2; ks++) {
            uint32_t afh[4][4], afl[4][4], bfh[4][2], bfl[4][2];
            #pragma unroll
            for (int mi = 0; mi < 4; mi++) {
                uint32_t off = aOff + (uint32_t)(mi * 16 * AST + ks * 16) * 2;
                ldsm4(aAddrH + off, afh[mi]);
                ldsm4(aAddrL + off, afl[mi]);
            }
            #pragma unroll
            for (int ni = 0; ni < 4; ni++) {
                uint32_t off = bOff + (uint32_t)(ks * 16 * BST + ni * 8) * 2;
                ldsm2t(bAddrH + off, bfh[ni]);
                ldsm2t(bAddrL + off, bfl[ni]);
            }
            #pragma unroll
            for (int mi = 0; mi < 4; mi++)
                #pragma unroll
                for (int ni = 0; ni < 4; ni++) {
                    mma16816(acc[mi][ni], afh[mi], bfh[ni]);
                    mma16816(acc[mi][ni], afh[mi], bfl[ni]);
                    mma16816(acc[mi][ni], afl[mi], bfh[ni]);
                }
        }

        // issue chunk it+2 into stage (it+2)%3 — safe: all warps passed the barrier,
        // so none is still reading that stage (it-1's readers are done).
        int nk = it + STG - 1;
        if (nk < nchunk) issue(nk * 32, nk % STG);
        cpasync_commit();       // empty group on tail keeps wait counts aligned
    }

    // epilogue
    const int gr = lane >> 2, gc = (lane & 3) * 2;
    #pragma unroll
    for (int mi = 0; mi < 4; mi++) {
        int r0 = mBase + warpM * 64 + mi * 16 + gr;
        #pragma unroll
        for (int ni = 0; ni < 4; ni++) {
            int col = nBase + warpN * 32 + ni * 8 + gc;
            if (GUARD && col >= N) continue;
            float b0 = bias[col], b1 = bias[col + 1];
            float v0 = acc[mi][ni][0] + b0, v1 = acc[mi][ni][1] + b1;
            float v2 = acc[mi][ni][2] + b0, v3 = acc[mi][ni][3] + b1;
            if (MODE == 1) {
                v0 = gelu_f(v0); v1 = gelu_f(v1); v2 = gelu_f(v2); v3 = gelu_f(v3);
                __nv_bfloat16 h0,h1,l0,l1;
                split2(v0,h0,l0); split2(v1,h1,l1);
                *(__nv_bfloat162*)(Ch + (size_t)r0 * N + col) = __nv_bfloat162(h0,h1);
                *(__nv_bfloat162*)(Cl + (size_t)r0 * N + col) = __nv_bfloat162(l0,l1);
                split2(v2,h0,l0); split2(v3,h1,l1);
                *(__nv_bfloat162*)(Ch + (size_t)(r0+8) * N + col) = __nv_bfloat162(h0,h1);
                *(__nv_bfloat162*)(Cl + (size_t)(r0+8) * N + col) = __nv_bfloat162(l0,l1);
            } else {
                if (MODE == 2) {
                    const float* rr0 = res + (size_t)r0 * N + col;
                    const float* rr1 = res + (size_t)(r0 + 8) * N + col;
                    v0 += rr0[0]; v1 += rr0[1]; v2 += rr1[0]; v3 += rr1[1];
                }
                *(float2*)(C + (size_t)r0 * N + col)       = make_float2(v0, v1);
                *(float2*)(C + (size_t)(r0 + 8) * N + col) = make_float2(v2, v3);
            }
        }
    }
}

// ---------------- launch ----------------
extern "C" void kernel_launch(void* const* d_in, const int* in_sizes, int n_in,
                              void* d_out, int out_size) {
    const int*   input_ids = (const int*)  d_in[0];
    const int*   type_ids  = (const int*)  d_in[1];
    const float* wte    = (const float*)d_in[2];
    const float* wtte   = (const float*)d_in[3];
    const float* wpe    = (const float*)d_in[4];
    const float* ln1_w  = (const float*)d_in[5];
    const float* ln1_b  = (const float*)d_in[6];
    const float* attn_w = (const float*)d_in[7];
    const float* attn_b = (const float*)d_in[8];
    const float* atp_w  = (const float*)d_in[9];
    const float* atp_b  = (const float*)d_in[10];
    const float* ln2_w  = (const float*)d_in[11];
    const float* ln2_b  = (const float*)d_in[12];
    const float* fc_w   = (const float*)d_in[13];
    const float* fc_b   = (const float*)d_in[14];
    const float* mlp_w  = (const float*)d_in[15];
    const float* mlp_b  = (const float*)d_in[16];
    const float* lnf_w  = (const float*)d_in[17];
    const float* lnf_b  = (const float*)d_in[18];
    const float* head_w = (const float*)d_in[19];
    const float* head_b = (const float*)d_in[20];
    float* out = (float*)d_out;

    float *h, *qkv;
    __nv_bfloat16 *xh, *xl, *mh, *ml;
    cudaGetSymbolAddress((void**)&h,   g_h);
    cudaGetSymbolAddress((void**)&qkv, g_qkv);
    cudaGetSymbolAddress((void**)&xh,  g_xh);  cudaGetSymbolAddress((void**)&xl, g_xl);
    cudaGetSymbolAddress((void**)&mh,  g_mh);  cudaGetSymbolAddress((void**)&ml, g_ml);

    __nv_bfloat16 *wqh, *wql, *wph, *wpl, *wfh, *wfl, *wmh, *wml, *whh, *whl;
    cudaGetSymbolAddress((void**)&wqh, g_wqkv_h); cudaGetSymbolAddress((void**)&wql, g_wqkv_l);
    cudaGetSymbolAddress((void**)&wph, g_watp_h); cudaGetSymbolAddress((void**)&wpl, g_watp_l);
    cudaGetSymbolAddress((void**)&wfh, g_wfc_h);  cudaGetSymbolAddress((void**)&wfl, g_wfc_l);
    cudaGetSymbolAddress((void**)&wmh, g_wmlp_h); cudaGetSymbolAddress((void**)&wml, g_wmlp_l);
    cudaGetSymbolAddress((void**)&whh, g_whead_h); cudaGetSymbolAddress((void**)&whl, g_whead_l);

    const int FA_SMEM = 4 * FA_TILE * (int)sizeof(__nv_bfloat16);
    cudaFuncSetAttribute(flash_attn_kernel,
                         cudaFuncAttributeMaxDynamicSharedMemorySize, FA_SMEM);
    cudaFuncSetAttribute(hgemm3_kernel<0, false>,
                         cudaFuncAttributeMaxDynamicSharedMemorySize, G3_SMEM);
    cudaFuncSetAttribute(hgemm3_kernel<1, false>,
                         cudaFuncAttributeMaxDynamicSharedMemorySize, G3_SMEM);
    cudaFuncSetAttribute(hgemm3_kernel<2, false>,
                         cudaFuncAttributeMaxDynamicSharedMemorySize, G3_SMEM);
    cudaFuncSetAttribute(hgemm3_kernel<0, true>,
                         cudaFuncAttributeMaxDynamicSharedMemorySize, G3_SMEM);

    // ---- pre-split weights ----
    {
        int n4;
        n4 = NLAYER * DIM * 3 * DIM / 4;
        wsplit_kernel<<<(n4 + 255) / 256, 256>>>(attn_w, wqh, wql, n4);
        n4 = NLAYER * DIM * DIM / 4;
        wsplit_kernel<<<(n4 + 255) / 256, 256>>>(atp_w, wph, wpl, n4);
        n4 = NLAYER * DIM * 4 * DIM / 4;
        wsplit_kernel<<<(n4 + 255) / 256, 256>>>(fc_w, wfh, wfl, n4);
        n4 = NLAYER * 4 * DIM * DIM / 4;
        wsplit_kernel<<<(n4 + 255) / 256, 256>>>(mlp_w, wmh, wml, n4);
        wsplit_head_kernel<<<dim3((VPAD + 255) / 256, DIM), 256>>>(head_w, whh, whl);
    }

    embed_kernel<<<MTOK, 256>>>(input_ids, type_ids, wte, wtte, wpe, h);

    for (int l = 0; l < NLAYER; l++) {
        const __nv_bfloat16* awh = wqh + (size_t)l * DIM * 3 * DIM;
        const __nv_bfloat16* awl = wql + (size_t)l * DIM * 3 * DIM;
        const __nv_bfloat16* pwh = wph + (size_t)l * DIM * DIM;
        const __nv_bfloat16* pwl = wpl + (size_t)l * DIM * DIM;
        const __nv_bfloat16* fwh = wfh + (size_t)l * DIM * 4 * DIM;
        const __nv_bfloat16* fwl = wfl + (size_t)l * DIM * 4 * DIM;
        const __nv_bfloat16* mwh = wmh + (size_t)l * 4 * DIM * DIM;
        const __nv_bfloat16* mwl = wml + (size_t)l * 4 * DIM * DIM;
        const float* ab = attn_b + (size_t)l * 3 * DIM;
        const float* pb = atp_b  + (size_t)l * DIM;
        const float* fb = fc_b   + (size_t)l * 4 * DIM;
        const float* mb = mlp_b  + (size_t)l * DIM;

        ln_bf_kernel<<<MTOK, 256>>>(h, xh, xl, ln1_w + l * DIM, ln1_b + l * DIM);
        hgemm3_kernel<0, false><<<dim3(3 * DIM / 128, MTOK / 128), 256, G3_SMEM>>>(
            xh, xl, awh, awl, 3 * DIM, ab, nullptr, qkv, nullptr, nullptr, MTOK, 3 * DIM, DIM);
        flash_attn_kernel<<<dim3(NQT, NHEAD, BATCH), 256, FA_SMEM>>>(qkv, xh, xl);
        hgemm3_kernel<2, false><<<dim3(DIM / 128, MTOK / 128), 256, G3_SMEM>>>(
            xh, xl, pwh, pwl, DIM, pb, h, h, nullptr, nullptr, MTOK, DIM, DIM);
        ln_bf_kernel<<<MTOK, 256>>>(h, xh, xl, ln2_w + l * DIM, ln2_b + l * DIM);
        hgemm3_kernel<1, false><<<dim3(4 * DIM / 128, MTOK / 128), 256, G3_SMEM>>>(
            xh, xl, fwh, fwl, 4 * DIM, fb, nullptr, nullptr, mh, ml, MTOK, 4 * DIM, DIM);
        hgemm3_kernel<2, false><<<dim3(DIM / 128, MTOK / 128), 256, G3_SMEM>>>(
            mh, ml, mwh, mwl, DIM, mb, h, h, nullptr, nullptr, MTOK, DIM, 4 * DIM);
    }

    ln_bf_kernel<<<MTOK, 256>>>(h, xh, xl, lnf_w, lnf_b);
    hgemm3_kernel<0, true><<<dim3(VPAD / 128, MTOK / 128), 256, G3_SMEM>>>(
        xh, xl, whh, whl, VPAD, head_b, nullptr, out, nullptr, nullptr, MTOK, VOCAB, DIM);
}